// round 1
// baseline (speedup 1.0000x reference)
#include <cuda_runtime.h>
#include <cstdint>

// ---------------- problem constants ----------------
constexpr int NAB  = 20000;
constexpr int NAG  = 20000;
constexpr int NTOT = NAB + NAG;      // 40000
constexpr int FF   = 256;
constexpr int EAB  = 320000;
constexpr int EAG  = 320000;
constexpr int ED   = 640000;
constexpr float EPS = 1e-5f;
constexpr float SLOPE = 0.2f;

// ---------------- scratch (device globals, no allocs) ----------------
__device__ float g_X[(size_t)NTOT * FF];   // relu(bn(gcn)) : GAT input + final "h"
__device__ float g_A[(size_t)NTOT * FF];   // gcn raw accum -> gat1 out -> gat2 out
__device__ float g_B[(size_t)NTOT * FF];   // gemm h buffer (both GAT layers, GCN h)
__device__ float g_deg[NTOT];              // deg -> dinv
__device__ float g_hs[NTOT], g_hd[NTOT], g_m[NTOT], g_s[NTOT], g_asf[NTOT];
__device__ float g_ex[ED];
__device__ float g_sum[1024], g_sq[1024], g_mu[1024], g_rstd[1024];

// ---------------- helpers ----------------
__device__ __forceinline__ float lrelu(float x) { return x > 0.f ? x : SLOPE * x; }

__device__ __forceinline__ void atomicMaxFloat(float* addr, float val) {
    if (val >= 0.f) atomicMax((int*)addr, __float_as_int(val));
    else            atomicMin((unsigned int*)addr, __float_as_uint(val));
}

// ---------------- tiny utility kernels ----------------
__global__ void k_fill(float* p, float v, int n) {
    int i = blockIdx.x * blockDim.x + threadIdx.x;
    if (i < n) p[i] = v;
}

__global__ void k_deg(const int* __restrict__ dst, int E, float* __restrict__ deg) {
    int i = blockIdx.x * blockDim.x + threadIdx.x;
    if (i < E) atomicAdd(&deg[dst[i]], 1.0f);
}

__global__ void k_rsqrt_inplace(float* p, int n) {
    int i = blockIdx.x * blockDim.x + threadIdx.x;
    if (i < n) p[i] = rsqrtf(p[i]);
}

// ---------------- SGEMM: C[M,256] = (relu?)A[M,256] @ W[256,256] ----------------
template<bool RELU>
__global__ void __launch_bounds__(256) k_gemm256(const float* __restrict__ A,
                                                 const float* __restrict__ W,
                                                 float* __restrict__ C, int M) {
    __shared__ float As[16][128];
    __shared__ float Bs[16][128];
    const int tid = threadIdx.x;
    const int m0 = blockIdx.x * 128;
    const int n0 = blockIdx.y * 128;
    const int tx = tid & 15, ty = tid >> 4;

    const int arow = tid >> 2;        // 0..63
    const int acol = (tid & 3) * 4;   // 0,4,8,12
    const int brow = tid >> 5;        // 0..7
    const int bcol = (tid & 31) * 4;  // 0..124

    float acc[8][8];
#pragma unroll
    for (int i = 0; i < 8; i++)
#pragma unroll
        for (int j = 0; j < 8; j++) acc[i][j] = 0.f;

    for (int k0 = 0; k0 < 256; k0 += 16) {
#pragma unroll
        for (int i = 0; i < 2; i++) {
            int r = m0 + arow + i * 64;
            int rc = r < M ? r : M - 1;
            float4 v = *(const float4*)(A + (size_t)rc * FF + k0 + acol);
            if (RELU) {
                v.x = fmaxf(v.x, 0.f); v.y = fmaxf(v.y, 0.f);
                v.z = fmaxf(v.z, 0.f); v.w = fmaxf(v.w, 0.f);
            }
            As[acol + 0][arow + i * 64] = v.x;
            As[acol + 1][arow + i * 64] = v.y;
            As[acol + 2][arow + i * 64] = v.z;
            As[acol + 3][arow + i * 64] = v.w;
        }
#pragma unroll
        for (int i = 0; i < 2; i++) {
            int kr = brow + i * 8;
            float4 v = *(const float4*)(W + (size_t)(k0 + kr) * FF + n0 + bcol);
            *(float4*)&Bs[kr][bcol] = v;
        }
        __syncthreads();
#pragma unroll
        for (int kk = 0; kk < 16; kk++) {
            float a[8], b[8];
#pragma unroll
            for (int i = 0; i < 8; i++) a[i] = As[kk][ty * 8 + i];
#pragma unroll
            for (int j = 0; j < 8; j++) b[j] = Bs[kk][tx * 8 + j];
#pragma unroll
            for (int i = 0; i < 8; i++)
#pragma unroll
                for (int j = 0; j < 8; j++) acc[i][j] = fmaf(a[i], b[j], acc[i][j]);
        }
        __syncthreads();
    }
#pragma unroll
    for (int i = 0; i < 8; i++) {
        int r = m0 + ty * 8 + i;
        if (r < M) {
            float4 v0 = make_float4(acc[i][0], acc[i][1], acc[i][2], acc[i][3]);
            float4 v1 = make_float4(acc[i][4], acc[i][5], acc[i][6], acc[i][7]);
            *(float4*)(C + (size_t)r * FF + n0 + tx * 8) = v0;
            *(float4*)(C + (size_t)r * FF + n0 + tx * 8 + 4) = v1;
        }
    }
}

// ---------------- GCN ----------------
// warp per edge: out[dst] += h[src] * dinv[src]*dinv[dst]
__global__ void k_gcn_edges(const int* __restrict__ src, const int* __restrict__ dst, int E,
                            const float* __restrict__ h, float* __restrict__ out,
                            const float* __restrict__ dinv) {
    int w = (blockIdx.x * blockDim.x + threadIdx.x) >> 5;
    int lane = threadIdx.x & 31;
    if (w >= E) return;
    int s = src[w], d = dst[w];
    float nm = dinv[s] * dinv[d];
    const float* hp = h + (size_t)s * FF;
    float* op = out + (size_t)d * FF;
#pragma unroll
    for (int j = 0; j < 8; j++) {
        int c = j * 32 + lane;
        atomicAdd(op + c, hp[c] * nm);
    }
}

// self loop + bias (plain RMW, runs after edge kernel)
__global__ void k_gcn_self(const float* __restrict__ h, float* __restrict__ out,
                           const float* __restrict__ dinv, const float* __restrict__ b, int n) {
    int idx = blockIdx.x * blockDim.x + threadIdx.x;
    if (idx >= n * FF) return;
    int i = idx >> 8, c = idx & 255;
    out[idx] += h[idx] * dinv[i] * dinv[i] + b[c];
}

// ---------------- BN ----------------
__global__ void k_stats(const float* __restrict__ X, int nrows,
                        float* __restrict__ sum, float* __restrict__ sq) {
    int c = threadIdx.x;  // 256 threads = 256 cols
    float s = 0.f, q = 0.f;
    for (int r = blockIdx.x; r < nrows; r += gridDim.x) {
        float v = X[(size_t)r * FF + c];
        s += v; q += v * v;
    }
    atomicAdd(&sum[c], s);
    atomicAdd(&sq[c], q);
}

__global__ void k_finalize(const float* __restrict__ sum, const float* __restrict__ sq,
                           float* __restrict__ mu, float* __restrict__ rstd, int n, int cnt) {
    int i = blockIdx.x * blockDim.x + threadIdx.x;
    if (i >= cnt) return;
    float m = sum[i] / n;
    mu[i] = m;
    rstd[i] = rsqrtf(sq[i] / n - m * m + EPS);
}

__global__ void k_bnrelu(const float* __restrict__ X, float* __restrict__ Y,
                         const float* __restrict__ mu, const float* __restrict__ rstd,
                         const float* __restrict__ g, const float* __restrict__ b, int n) {
    int idx = blockIdx.x * blockDim.x + threadIdx.x;
    if (idx >= n * FF) return;
    int c = idx & 255;
    float v = (X[idx] - mu[c]) * rstd[c] * g[c] + b[c];
    Y[idx] = fmaxf(v, 0.f);
}

// ---------------- GAT ----------------
// warp per node: hs = h . a_s ; hd = h . a_d
__global__ void k_hshd(const float* __restrict__ h, const float* __restrict__ as_,
                       const float* __restrict__ ad_, float* __restrict__ hs,
                       float* __restrict__ hd, int n) {
    int w = (blockIdx.x * blockDim.x + threadIdx.x) >> 5;
    int lane = threadIdx.x & 31;
    if (w >= n) return;
    const float* hp = h + (size_t)w * FF;
    float s1 = 0.f, s2 = 0.f;
#pragma unroll
    for (int j = 0; j < 8; j++) {
        int c = j * 32 + lane;
        float v = hp[c];
        s1 += v * __ldg(as_ + c);
        s2 += v * __ldg(ad_ + c);
    }
#pragma unroll
    for (int off = 16; off > 0; off >>= 1) {
        s1 += __shfl_down_sync(0xffffffff, s1, off);
        s2 += __shfl_down_sync(0xffffffff, s2, off);
    }
    if (lane == 0) { hs[w] = s1; hd[w] = s2; }
}

__global__ void k_init_m(const float* __restrict__ hs, const float* __restrict__ hd,
                         float* __restrict__ m, int n) {
    int i = blockIdx.x * blockDim.x + threadIdx.x;
    if (i < n) m[i] = lrelu(hs[i] + hd[i]);   // self-loop score seeds the max
}

__global__ void k_edge_max(const int* __restrict__ src, const int* __restrict__ dst, int E,
                           const float* __restrict__ hs, const float* __restrict__ hd,
                           float* __restrict__ m) {
    int i = blockIdx.x * blockDim.x + threadIdx.x;
    if (i >= E) return;
    int d = dst[i];
    float e = lrelu(hs[src[i]] + hd[d]);
    atomicMaxFloat(&m[d], e);
}

__global__ void k_init_s(const float* __restrict__ hs, const float* __restrict__ hd,
                         const float* __restrict__ m, float* __restrict__ s, int n) {
    int i = blockIdx.x * blockDim.x + threadIdx.x;
    if (i < n) s[i] = expf(lrelu(hs[i] + hd[i]) - m[i]);   // self term seeds the sum
}

__global__ void k_edge_sum(const int* __restrict__ src, const int* __restrict__ dst, int E,
                           const float* __restrict__ hs, const float* __restrict__ hd,
                           const float* __restrict__ m, float* __restrict__ s,
                           float* __restrict__ ex) {
    int i = blockIdx.x * blockDim.x + threadIdx.x;
    if (i >= E) return;
    int d = dst[i];
    float e = lrelu(hs[src[i]] + hd[d]);
    float x = expf(e - m[d]);
    ex[i] = x;
    atomicAdd(&s[d], x);
}

__global__ void k_alpha_self(const float* __restrict__ hs, const float* __restrict__ hd,
                             const float* __restrict__ m, const float* __restrict__ s,
                             float* __restrict__ asf, int n) {
    int i = blockIdx.x * blockDim.x + threadIdx.x;
    if (i < n) asf[i] = expf(lrelu(hs[i] + hd[i]) - m[i]) / s[i];
}

// initializes out = h * alpha_self + b  (no pre-zero needed)
__global__ void k_self_out(const float* __restrict__ h, float* __restrict__ out,
                           const float* __restrict__ asf, const float* __restrict__ b, int n) {
    int idx = blockIdx.x * blockDim.x + threadIdx.x;
    if (idx >= n * FF) return;
    int i = idx >> 8, c = idx & 255;
    out[idx] = h[idx] * asf[i] + b[c];
}

// warp per edge: out[dst] += h[src] * (ex[e]/s[dst])
__global__ void k_edge_aggr(const int* __restrict__ src, const int* __restrict__ dst, int E,
                            const float* __restrict__ h, float* __restrict__ out,
                            const float* __restrict__ ex, const float* __restrict__ s) {
    int w = (blockIdx.x * blockDim.x + threadIdx.x) >> 5;
    int lane = threadIdx.x & 31;
    if (w >= E) return;
    int sn = src[w], d = dst[w];
    float alpha = ex[w] / s[d];
    const float* hp = h + (size_t)sn * FF;
    float* op = out + (size_t)d * FF;
#pragma unroll
    for (int j = 0; j < 8; j++) {
        int c = j * 32 + lane;
        atomicAdd(op + c, hp[c] * alpha);
    }
}

// ---------------- final: relu(bn(concat[X,H])) @ Wfc + bfc ----------------
__global__ void k_final(const float* __restrict__ Xp, const float* __restrict__ Hp,
                        const float* __restrict__ mu, const float* __restrict__ rstd,
                        const float* __restrict__ g, const float* __restrict__ b,
                        const float* __restrict__ Wfc, const float* __restrict__ bfc,
                        float* __restrict__ out, int n) {
    int w = (blockIdx.x * blockDim.x + threadIdx.x) >> 5;
    int lane = threadIdx.x & 31;
    if (w >= n) return;
    float acc = 0.f;
#pragma unroll
    for (int j = 0; j < 16; j++) {
        int c = j * 32 + lane;
        float v = (c < FF) ? Xp[(size_t)w * FF + c] : Hp[(size_t)w * FF + (c - FF)];
        v = (v - mu[c]) * rstd[c] * g[c] + b[c];
        v = fmaxf(v, 0.f);
        acc += v * __ldg(Wfc + c);
    }
#pragma unroll
    for (int off = 16; off > 0; off >>= 1) acc += __shfl_down_sync(0xffffffff, acc, off);
    if (lane == 0) out[w] = acc + bfc[0];
}

// ---------------- host orchestration ----------------
static void gat_layer(const float* xin, bool relu_in, const float* W, const float* a_s,
                      const float* a_d, const float* b, float* hbuf, float* outbuf,
                      const int* esrc, const int* edst, int E,
                      float* hs, float* hd, float* m, float* s, float* asf, float* ex) {
    dim3 gg((NTOT + 127) / 128, 2);
    if (relu_in) k_gemm256<true><<<gg, 256>>>(xin, W, hbuf, NTOT);
    else         k_gemm256<false><<<gg, 256>>>(xin, W, hbuf, NTOT);
    k_hshd<<<(NTOT * 32 + 255) / 256, 256>>>(hbuf, a_s, a_d, hs, hd, NTOT);
    k_init_m<<<(NTOT + 255) / 256, 256>>>(hs, hd, m, NTOT);
    k_edge_max<<<(E + 255) / 256, 256>>>(esrc, edst, E, hs, hd, m);
    k_init_s<<<(NTOT + 255) / 256, 256>>>(hs, hd, m, s, NTOT);
    k_edge_sum<<<(E + 255) / 256, 256>>>(esrc, edst, E, hs, hd, m, s, ex);
    k_alpha_self<<<(NTOT + 255) / 256, 256>>>(hs, hd, m, s, asf, NTOT);
    k_self_out<<<(NTOT * FF + 255) / 256, 256>>>(hbuf, outbuf, asf, b, NTOT);
    k_edge_aggr<<<((size_t)E * 32 + 255) / 256, 256>>>(esrc, edst, E, hbuf, outbuf, ex, s);
}

extern "C" void kernel_launch(void* const* d_in, const int* in_sizes, int n_in,
                              void* d_out, int out_size) {
    const float* x_ab   = (const float*)d_in[0];
    const float* x_ag   = (const float*)d_in[1];
    const float* W_gcn  = (const float*)d_in[2];
    const float* b_gcn  = (const float*)d_in[3];
    const float* g1     = (const float*)d_in[4];
    const float* be1    = (const float*)d_in[5];
    const float* W_aggcn= (const float*)d_in[6];
    const float* b_aggcn= (const float*)d_in[7];
    const float* ag_g1  = (const float*)d_in[8];
    const float* ag_be1 = (const float*)d_in[9];
    const float* W_gat  = (const float*)d_in[10];
    const float* a_src  = (const float*)d_in[11];
    const float* a_dst  = (const float*)d_in[12];
    const float* b_gat  = (const float*)d_in[13];
    const float* W_gat2 = (const float*)d_in[14];
    const float* a_src2 = (const float*)d_in[15];
    const float* a_dst2 = (const float*)d_in[16];
    const float* b_gat2 = (const float*)d_in[17];
    const float* ag_g2  = (const float*)d_in[18];
    const float* ag_be2 = (const float*)d_in[19];
    const float* W_agfc = (const float*)d_in[20];
    const float* b_agfc = (const float*)d_in[21];
    const float* g2     = (const float*)d_in[22];
    const float* be2    = (const float*)d_in[23];
    const float* W_fc   = (const float*)d_in[24];
    const float* b_fc   = (const float*)d_in[25];
    const int* e_ab     = (const int*)d_in[26];
    const int* e_ag     = (const int*)d_in[27];
    const int* e_d      = (const int*)d_in[28];
    float* out = (float*)d_out;

    float *pX, *pA, *pB, *pdeg, *phs, *phd, *pm, *ps, *pasf, *pex, *psum, *psq, *pmu, *prstd;
    cudaGetSymbolAddress((void**)&pX, g_X);
    cudaGetSymbolAddress((void**)&pA, g_A);
    cudaGetSymbolAddress((void**)&pB, g_B);
    cudaGetSymbolAddress((void**)&pdeg, g_deg);
    cudaGetSymbolAddress((void**)&phs, g_hs);
    cudaGetSymbolAddress((void**)&phd, g_hd);
    cudaGetSymbolAddress((void**)&pm, g_m);
    cudaGetSymbolAddress((void**)&ps, g_s);
    cudaGetSymbolAddress((void**)&pasf, g_asf);
    cudaGetSymbolAddress((void**)&pex, g_ex);
    cudaGetSymbolAddress((void**)&psum, g_sum);
    cudaGetSymbolAddress((void**)&psq, g_sq);
    cudaGetSymbolAddress((void**)&pmu, g_mu);
    cudaGetSymbolAddress((void**)&prstd, g_rstd);

    const int* eab_src = e_ab;           const int* eab_dst = e_ab + EAB;
    const int* eag_src = e_ag;           const int* eag_dst = e_ag + EAG;
    const int* ed_src  = e_d;            const int* ed_dst  = e_d + ED;

    // ---- degree / dinv ----
    k_fill<<<(NTOT + 255) / 256, 256>>>(pdeg, 1.0f, NTOT);   // self-loop
    k_deg<<<(EAB + 255) / 256, 256>>>(eab_dst, EAB, pdeg);
    k_deg<<<(EAG + 255) / 256, 256>>>(eag_dst, EAG, pdeg + NAB);
    k_rsqrt_inplace<<<(NTOT + 255) / 256, 256>>>(pdeg, NTOT);

    // ---- GCN GEMMs: h into g_B (ab rows 0.., ag rows NAB..) ----
    {
        dim3 gab((NAB + 127) / 128, 2);
        k_gemm256<false><<<gab, 256>>>(x_ab, W_gcn, pB, NAB);
        k_gemm256<false><<<gab, 256>>>(x_ag, W_aggcn, pB + (size_t)NAB * FF, NAB);
    }
    // ---- GCN aggregate into g_A ----
    k_fill<<<((size_t)NTOT * FF + 255) / 256, 256>>>(pA, 0.f, NTOT * FF);
    k_gcn_edges<<<((size_t)EAB * 32 + 255) / 256, 256>>>(eab_src, eab_dst, EAB, pB, pA, pdeg);
    k_gcn_edges<<<((size_t)EAG * 32 + 255) / 256, 256>>>(eag_src, eag_dst, EAG,
                 pB + (size_t)NAB * FF, pA + (size_t)NAB * FF, pdeg + NAB);
    k_gcn_self<<<((size_t)NAB * FF + 255) / 256, 256>>>(pB, pA, pdeg, b_gcn, NAB);
    k_gcn_self<<<((size_t)NAB * FF + 255) / 256, 256>>>(pB + (size_t)NAB * FF,
                 pA + (size_t)NAB * FF, pdeg + NAB, b_aggcn, NAB);

    // ---- BN1 + relu -> g_X ----
    k_fill<<<4, 256>>>(psum, 0.f, 1024);
    k_fill<<<4, 256>>>(psq, 0.f, 1024);
    k_stats<<<96, 256>>>(pA, NAB, psum, psq);
    k_stats<<<96, 256>>>(pA + (size_t)NAB * FF, NAB, psum + 256, psq + 256);
    k_finalize<<<4, 256>>>(psum, psq, pmu, prstd, NAB, 512);
    k_bnrelu<<<((size_t)NAB * FF + 255) / 256, 256>>>(pA, pX, pmu, prstd, g1, be1, NAB);
    k_bnrelu<<<((size_t)NAB * FF + 255) / 256, 256>>>(pA + (size_t)NAB * FF,
                 pX + (size_t)NAB * FF, pmu + 256, prstd + 256, ag_g1, ag_be1, NAB);

    // ---- GAT1: g_X -> g_A (h in g_B); GAT2: relu(g_A) -> g_A ----
    gat_layer(pX, false, W_gat,  a_src,  a_dst,  b_gat,  pB, pA, ed_src, ed_dst, ED,
              phs, phd, pm, ps, pasf, pex);
    gat_layer(pA, true,  W_gat2, a_src2, a_dst2, b_gat2, pB, pA, ed_src, ed_dst, ED,
              phs, phd, pm, ps, pasf, pex);

    // ---- final BN stats over concat halves ----
    k_fill<<<4, 256>>>(psum, 0.f, 1024);
    k_fill<<<4, 256>>>(psq, 0.f, 1024);
    k_stats<<<96, 256>>>(pA, NAB, psum, psq);                                  // x1
    k_stats<<<96, 256>>>(pX, NAB, psum + 256, psq + 256);                      // h_ab
    k_stats<<<96, 256>>>(pA + (size_t)NAB * FF, NAG, psum + 512, psq + 512);   // x2
    k_stats<<<96, 256>>>(pX + (size_t)NAB * FF, NAG, psum + 768, psq + 768);   // h_ag
    k_finalize<<<4, 256>>>(psum, psq, pmu, prstd, NAB, 1024);

    // ---- final outputs ----
    k_final<<<(NAB * 32 + 255) / 256, 256>>>(pA, pX, pmu, prstd, g2, be2, W_fc, b_fc,
                                             out, NAB);
    k_final<<<(NAG * 32 + 255) / 256, 256>>>(pA + (size_t)NAB * FF, pX + (size_t)NAB * FF,
                                             pmu + 512, prstd + 512, ag_g2, ag_be2,
                                             W_agfc, b_agfc, out + NAB, NAG);
}

// round 3
// speedup vs baseline: 1.1144x; 1.1144x over previous
#include <cuda_runtime.h>
#include <cstdint>

// ---------------- problem constants ----------------
constexpr int NAB  = 20000;
constexpr int NAG  = 20000;
constexpr int NTOT = NAB + NAG;      // 40000
constexpr int FF   = 256;
constexpr int EAB  = 320000;
constexpr int EAG  = 320000;
constexpr int ED   = 640000;
constexpr float EPS = 1e-5f;
constexpr float SLOPE = 0.2f;
constexpr float NINF = -3.0e38f;

// ---------------- scratch (device globals, no allocs) ----------------
__device__ float g_X[(size_t)NTOT * FF];   // relu(bn(gcn)) : GAT input + final "h"
__device__ float g_A[(size_t)NTOT * FF];   // gcn out -> gat1 out -> gat2 out
__device__ float g_B[(size_t)NTOT * FF];   // gemm h buffer
__device__ float g_dinv[NTOT];
__device__ float g_hs[NTOT], g_hd[NTOT];
__device__ float g_sum[1024], g_sq[1024], g_mu[1024], g_rstd[1024];

// CSR scratch
__device__ int g_degi[NTOT];
__device__ int g_cur[NTOT];
__device__ int g_off_ab[NAB + 1];
__device__ int g_off_ag[NAG + 1];
__device__ int g_off_d[NTOT + 1];
__device__ int g_csr_ab[EAB];
__device__ int g_csr_ag[EAG];
__device__ int g_csr_d[ED];

// ---------------- helpers ----------------
__device__ __forceinline__ float lrelu(float x) { return x > 0.f ? x : SLOPE * x; }

// ---------------- tiny utility kernels ----------------
__global__ void k_filli(int* p, int v, int n) {
    int i = blockIdx.x * blockDim.x + threadIdx.x;
    if (i < n) p[i] = v;
}
__global__ void k_fill(float* p, float v, int n) {
    int i = blockIdx.x * blockDim.x + threadIdx.x;
    if (i < n) p[i] = v;
}
__global__ void k_copyi(const int* __restrict__ a, int* __restrict__ b, int n) {
    int i = blockIdx.x * blockDim.x + threadIdx.x;
    if (i < n) b[i] = a[i];
}
__global__ void k_deg(const int* __restrict__ dst, int E, int* __restrict__ deg) {
    int i = blockIdx.x * blockDim.x + threadIdx.x;
    if (i < E) atomicAdd(&deg[dst[i]], 1);
}
__global__ void k_dinv(const int* __restrict__ deg, float* __restrict__ dinv, int n) {
    int i = blockIdx.x * blockDim.x + threadIdx.x;
    if (i < n) dinv[i] = rsqrtf((float)deg[i] + 1.0f);   // +1 for self loop
}

// single-block exclusive scan: off[0..n] from deg[0..n)
__global__ void __launch_bounds__(1024) k_scan(const int* __restrict__ deg,
                                               int* __restrict__ off, int n) {
    __shared__ int ssum[1024];
    int t = threadIdx.x;
    int C = (n + 1023) / 1024;
    int lo = t * C, hi = min(lo + C, n);
    if (lo > n) lo = n;
    int s = 0;
    for (int i = lo; i < hi; i++) s += deg[i];
    ssum[t] = s;
    __syncthreads();
    for (int d = 1; d < 1024; d <<= 1) {
        int v = (t >= d) ? ssum[t - d] : 0;
        __syncthreads();
        if (t >= d) ssum[t] += v;
        __syncthreads();
    }
    int run = (t > 0) ? ssum[t - 1] : 0;
    for (int i = lo; i < hi; i++) { off[i] = run; run += deg[i]; }
    if (t == 0) off[n] = ssum[1023];
}

__global__ void k_scatter(const int* __restrict__ src, const int* __restrict__ dst, int E,
                          int* __restrict__ cur, int* __restrict__ csr, int dstbase) {
    int i = blockIdx.x * blockDim.x + threadIdx.x;
    if (i >= E) return;
    int pos = atomicAdd(&cur[dst[i] + dstbase], 1);
    csr[pos] = src[i];
}

// ---------------- SGEMM: C[M,256] = (relu?)A[M,256] @ W[256,256] ----------------
template<bool RELU>
__global__ void __launch_bounds__(256) k_gemm256(const float* __restrict__ A,
                                                 const float* __restrict__ W,
                                                 float* __restrict__ C, int M) {
    __shared__ float As[16][128];
    __shared__ float Bs[16][128];
    const int tid = threadIdx.x;
    const int m0 = blockIdx.x * 128;
    const int n0 = blockIdx.y * 128;
    const int tx = tid & 15, ty = tid >> 4;

    const int arow = tid >> 2;
    const int acol = (tid & 3) * 4;
    const int brow = tid >> 5;
    const int bcol = (tid & 31) * 4;

    float acc[8][8];
#pragma unroll
    for (int i = 0; i < 8; i++)
#pragma unroll
        for (int j = 0; j < 8; j++) acc[i][j] = 0.f;

    for (int k0 = 0; k0 < 256; k0 += 16) {
#pragma unroll
        for (int i = 0; i < 2; i++) {
            int r = m0 + arow + i * 64;
            int rc = r < M ? r : M - 1;
            float4 v = *(const float4*)(A + (size_t)rc * FF + k0 + acol);
            if (RELU) {
                v.x = fmaxf(v.x, 0.f); v.y = fmaxf(v.y, 0.f);
                v.z = fmaxf(v.z, 0.f); v.w = fmaxf(v.w, 0.f);
            }
            As[acol + 0][arow + i * 64] = v.x;
            As[acol + 1][arow + i * 64] = v.y;
            As[acol + 2][arow + i * 64] = v.z;
            As[acol + 3][arow + i * 64] = v.w;
        }
#pragma unroll
        for (int i = 0; i < 2; i++) {
            int kr = brow + i * 8;
            float4 v = *(const float4*)(W + (size_t)(k0 + kr) * FF + n0 + bcol);
            *(float4*)&Bs[kr][bcol] = v;
        }
        __syncthreads();
#pragma unroll
        for (int kk = 0; kk < 16; kk++) {
            float a[8], b[8];
#pragma unroll
            for (int i = 0; i < 8; i++) a[i] = As[kk][ty * 8 + i];
#pragma unroll
            for (int j = 0; j < 8; j++) b[j] = Bs[kk][tx * 8 + j];
#pragma unroll
            for (int i = 0; i < 8; i++)
#pragma unroll
                for (int j = 0; j < 8; j++) acc[i][j] = fmaf(a[i], b[j], acc[i][j]);
        }
        __syncthreads();
    }
#pragma unroll
    for (int i = 0; i < 8; i++) {
        int r = m0 + ty * 8 + i;
        if (r < M) {
            float4 v0 = make_float4(acc[i][0], acc[i][1], acc[i][2], acc[i][3]);
            float4 v1 = make_float4(acc[i][4], acc[i][5], acc[i][6], acc[i][7]);
            *(float4*)(C + (size_t)r * FF + n0 + tx * 8) = v0;
            *(float4*)(C + (size_t)r * FF + n0 + tx * 8 + 4) = v1;
        }
    }
}

// ---------------- GCN gather: warp per node ----------------
// out[n] = (sum_{s in nbr(n)} h[s]*dinv[s] + h[n]*dinv[n]) * dinv[n] + b
__global__ void k_gcn_gather(const int* __restrict__ off, const int* __restrict__ csr,
                             const float* __restrict__ h, float* __restrict__ out,
                             const float* __restrict__ dinv, const float* __restrict__ b,
                             int n) {
    int w = (blockIdx.x * blockDim.x + threadIdx.x) >> 5;
    int lane = threadIdx.x & 31;
    if (w >= n) return;
    int e0 = off[w], e1 = off[w + 1];
    float dv = dinv[w];
    float4 a0 = make_float4(0.f, 0.f, 0.f, 0.f);
    float4 a1 = make_float4(0.f, 0.f, 0.f, 0.f);
    for (int base = e0; base < e1; base += 32) {
        int e = base + lane;
        int idx = (e < e1) ? csr[e] : 0;
        float wv = (e < e1) ? dinv[idx] : 0.f;
        int cnt = min(32, e1 - base);
        for (int k = 0; k < cnt; k++) {
            int s = __shfl_sync(0xffffffffu, idx, k);
            float ws = __shfl_sync(0xffffffffu, wv, k);
            const float4* hp = (const float4*)(h + (size_t)s * FF) + lane;
            float4 v0 = hp[0];
            float4 v1 = hp[32];
            a0.x += v0.x * ws; a0.y += v0.y * ws; a0.z += v0.z * ws; a0.w += v0.w * ws;
            a1.x += v1.x * ws; a1.y += v1.y * ws; a1.z += v1.z * ws; a1.w += v1.w * ws;
        }
    }
    // self loop
    {
        const float4* hp = (const float4*)(h + (size_t)w * FF) + lane;
        float4 v0 = hp[0], v1 = hp[32];
        a0.x += v0.x * dv; a0.y += v0.y * dv; a0.z += v0.z * dv; a0.w += v0.w * dv;
        a1.x += v1.x * dv; a1.y += v1.y * dv; a1.z += v1.z * dv; a1.w += v1.w * dv;
    }
    float4 b0 = *((const float4*)b + lane);
    float4 b1 = *((const float4*)b + lane + 32);
    float4 o0 = make_float4(a0.x * dv + b0.x, a0.y * dv + b0.y, a0.z * dv + b0.z, a0.w * dv + b0.w);
    float4 o1 = make_float4(a1.x * dv + b1.x, a1.y * dv + b1.y, a1.z * dv + b1.z, a1.w * dv + b1.w);
    float4* op = (float4*)(out + (size_t)w * FF) + lane;
    op[0] = o0;
    op[32] = o1;
}

// ---------------- BN ----------------
__global__ void k_stats(const float* __restrict__ X, int nrows,
                        float* __restrict__ sum, float* __restrict__ sq) {
    int c = threadIdx.x;
    float s = 0.f, q = 0.f;
    for (int r = blockIdx.x; r < nrows; r += gridDim.x) {
        float v = X[(size_t)r * FF + c];
        s += v; q += v * v;
    }
    atomicAdd(&sum[c], s);
    atomicAdd(&sq[c], q);
}

__global__ void k_finalize(const float* __restrict__ sum, const float* __restrict__ sq,
                           float* __restrict__ mu, float* __restrict__ rstd, int n, int cnt) {
    int i = blockIdx.x * blockDim.x + threadIdx.x;
    if (i >= cnt) return;
    float m = sum[i] / n;
    mu[i] = m;
    rstd[i] = rsqrtf(sq[i] / n - m * m + EPS);
}

__global__ void k_bnrelu(const float* __restrict__ X, float* __restrict__ Y,
                         const float* __restrict__ mu, const float* __restrict__ rstd,
                         const float* __restrict__ g, const float* __restrict__ b, int n) {
    int idx = blockIdx.x * blockDim.x + threadIdx.x;
    if (idx >= n * FF) return;
    int c = idx & 255;
    float v = (X[idx] - mu[c]) * rstd[c] * g[c] + b[c];
    Y[idx] = fmaxf(v, 0.f);
}

// ---------------- GAT ----------------
__global__ void k_hshd(const float* __restrict__ h, const float* __restrict__ as_,
                       const float* __restrict__ ad_, float* __restrict__ hs,
                       float* __restrict__ hd, int n) {
    int w = (blockIdx.x * blockDim.x + threadIdx.x) >> 5;
    int lane = threadIdx.x & 31;
    if (w >= n) return;
    const float* hp = h + (size_t)w * FF;
    float s1 = 0.f, s2 = 0.f;
#pragma unroll
    for (int j = 0; j < 8; j++) {
        int c = j * 32 + lane;
        float v = hp[c];
        s1 += v * __ldg(as_ + c);
        s2 += v * __ldg(ad_ + c);
    }
#pragma unroll
    for (int off = 16; off > 0; off >>= 1) {
        s1 += __shfl_down_sync(0xffffffffu, s1, off);
        s2 += __shfl_down_sync(0xffffffffu, s2, off);
    }
    if (lane == 0) { hs[w] = s1; hd[w] = s2; }
}

// fused GAT per node: online softmax over incoming edges + self, then gather.
__global__ void k_gat_node(const int* __restrict__ off, const int* __restrict__ csr,
                           const float* __restrict__ h, float* __restrict__ out,
                           const float* __restrict__ hs, const float* __restrict__ hd,
                           const float* __restrict__ b, int n) {
    int w = (blockIdx.x * blockDim.x + threadIdx.x) >> 5;
    int lane = threadIdx.x & 31;
    if (w >= n) return;
    int e0 = off[w], e1 = off[w + 1];
    float hdn = hd[w];
    float self_e = lrelu(hs[w] + hdn);

    // online (m, s) per lane; lane 0 seeds with the self term
    float m = (lane == 0) ? self_e : NINF;
    float s = (lane == 0) ? 1.f : 0.f;
    for (int e = e0 + lane; e < e1; e += 32) {
        float v = lrelu(hs[csr[e]] + hdn);
        if (v > m) { s = s * __expf(m - v) + 1.f; m = v; }
        else       { s += __expf(v - m); }
    }
    // merge across lanes (butterfly — all lanes converge)
#pragma unroll
    for (int o = 16; o > 0; o >>= 1) {
        float mo = __shfl_xor_sync(0xffffffffu, m, o);
        float so = __shfl_xor_sync(0xffffffffu, s, o);
        float mn = fmaxf(m, mo);
        s = s * __expf(m - mn) + so * __expf(mo - mn);
        m = mn;
    }
    float inv = 1.f / s;

    // aggregation
    float4 a0, a1;
    {
        float sa = __expf(self_e - m) * inv;
        const float4* hp = (const float4*)(h + (size_t)w * FF) + lane;
        float4 v0 = hp[0], v1 = hp[32];
        a0 = make_float4(v0.x * sa, v0.y * sa, v0.z * sa, v0.w * sa);
        a1 = make_float4(v1.x * sa, v1.y * sa, v1.z * sa, v1.w * sa);
    }
    for (int base = e0; base < e1; base += 32) {
        int e = base + lane;
        int idx = (e < e1) ? csr[e] : 0;
        float al = 0.f;
        if (e < e1) al = __expf(lrelu(hs[idx] + hdn) - m) * inv;
        int cnt = min(32, e1 - base);
        for (int k = 0; k < cnt; k++) {
            int sn = __shfl_sync(0xffffffffu, idx, k);
            float av = __shfl_sync(0xffffffffu, al, k);
            const float4* hp = (const float4*)(h + (size_t)sn * FF) + lane;
            float4 v0 = hp[0];
            float4 v1 = hp[32];
            a0.x += v0.x * av; a0.y += v0.y * av; a0.z += v0.z * av; a0.w += v0.w * av;
            a1.x += v1.x * av; a1.y += v1.y * av; a1.z += v1.z * av; a1.w += v1.w * av;
        }
    }
    float4 b0 = *((const float4*)b + lane);
    float4 b1 = *((const float4*)b + lane + 32);
    a0.x += b0.x; a0.y += b0.y; a0.z += b0.z; a0.w += b0.w;
    a1.x += b1.x; a1.y += b1.y; a1.z += b1.z; a1.w += b1.w;
    float4* op = (float4*)(out + (size_t)w * FF) + lane;
    op[0] = a0;
    op[32] = a1;
}

// ---------------- final: relu(bn(concat[X,H])) @ Wfc + bfc ----------------
__global__ void k_final(const float* __restrict__ Xp, const float* __restrict__ Hp,
                        const float* __restrict__ mu, const float* __restrict__ rstd,
                        const float* __restrict__ g, const float* __restrict__ b,
                        const float* __restrict__ Wfc, const float* __restrict__ bfc,
                        float* __restrict__ out, int n) {
    int w = (blockIdx.x * blockDim.x + threadIdx.x) >> 5;
    int lane = threadIdx.x & 31;
    if (w >= n) return;
    float acc = 0.f;
#pragma unroll
    for (int j = 0; j < 16; j++) {
        int c = j * 32 + lane;
        float v = (c < FF) ? Xp[(size_t)w * FF + c] : Hp[(size_t)w * FF + (c - FF)];
        v = (v - mu[c]) * rstd[c] * g[c] + b[c];
        v = fmaxf(v, 0.f);
        acc += v * __ldg(Wfc + c);
    }
#pragma unroll
    for (int off = 16; off > 0; off >>= 1) acc += __shfl_down_sync(0xffffffffu, acc, off);
    if (lane == 0) out[w] = acc + bfc[0];
}

// ---------------- host orchestration ----------------
static void gat_layer(const float* xin, bool relu_in, const float* W, const float* a_s,
                      const float* a_d, const float* b, float* hbuf, float* outbuf,
                      const int* off, const int* csr,
                      float* hs, float* hd) {
    dim3 gg((NTOT + 127) / 128, 2);
    if (relu_in) k_gemm256<true><<<gg, 256>>>(xin, W, hbuf, NTOT);
    else         k_gemm256<false><<<gg, 256>>>(xin, W, hbuf, NTOT);
    k_hshd<<<(NTOT * 32 + 255) / 256, 256>>>(hbuf, a_s, a_d, hs, hd, NTOT);
    k_gat_node<<<(NTOT * 32 + 255) / 256, 256>>>(off, csr, hbuf, outbuf, hs, hd, b, NTOT);
}

extern "C" void kernel_launch(void* const* d_in, const int* in_sizes, int n_in,
                              void* d_out, int out_size) {
    const float* x_ab   = (const float*)d_in[0];
    const float* x_ag   = (const float*)d_in[1];
    const float* W_gcn  = (const float*)d_in[2];
    const float* b_gcn  = (const float*)d_in[3];
    const float* g1     = (const float*)d_in[4];
    const float* be1    = (const float*)d_in[5];
    const float* W_aggcn= (const float*)d_in[6];
    const float* b_aggcn= (const float*)d_in[7];
    const float* ag_g1  = (const float*)d_in[8];
    const float* ag_be1 = (const float*)d_in[9];
    const float* W_gat  = (const float*)d_in[10];
    const float* a_src  = (const float*)d_in[11];
    const float* a_dst  = (const float*)d_in[12];
    const float* b_gat  = (const float*)d_in[13];
    const float* W_gat2 = (const float*)d_in[14];
    const float* a_src2 = (const float*)d_in[15];
    const float* a_dst2 = (const float*)d_in[16];
    const float* b_gat2 = (const float*)d_in[17];
    const float* ag_g2  = (const float*)d_in[18];
    const float* ag_be2 = (const float*)d_in[19];
    const float* W_agfc = (const float*)d_in[20];
    const float* b_agfc = (const float*)d_in[21];
    const float* g2     = (const float*)d_in[22];
    const float* be2    = (const float*)d_in[23];
    const float* W_fc   = (const float*)d_in[24];
    const float* b_fc   = (const float*)d_in[25];
    const int* e_ab     = (const int*)d_in[26];
    const int* e_ag     = (const int*)d_in[27];
    const int* e_d      = (const int*)d_in[28];
    float* out = (float*)d_out;

    float *pX, *pA, *pB, *pdinv, *phs, *phd, *psum, *psq, *pmu, *prstd;
    int *pdegi, *pcur, *poff_ab, *poff_ag, *poff_d, *pcsr_ab, *pcsr_ag, *pcsr_d;
    cudaGetSymbolAddress((void**)&pX, g_X);
    cudaGetSymbolAddress((void**)&pA, g_A);
    cudaGetSymbolAddress((void**)&pB, g_B);
    cudaGetSymbolAddress((void**)&pdinv, g_dinv);
    cudaGetSymbolAddress((void**)&phs, g_hs);
    cudaGetSymbolAddress((void**)&phd, g_hd);
    cudaGetSymbolAddress((void**)&psum, g_sum);
    cudaGetSymbolAddress((void**)&psq, g_sq);
    cudaGetSymbolAddress((void**)&pmu, g_mu);
    cudaGetSymbolAddress((void**)&prstd, g_rstd);
    cudaGetSymbolAddress((void**)&pdegi, g_degi);
    cudaGetSymbolAddress((void**)&pcur, g_cur);
    cudaGetSymbolAddress((void**)&poff_ab, g_off_ab);
    cudaGetSymbolAddress((void**)&poff_ag, g_off_ag);
    cudaGetSymbolAddress((void**)&poff_d, g_off_d);
    cudaGetSymbolAddress((void**)&pcsr_ab, g_csr_ab);
    cudaGetSymbolAddress((void**)&pcsr_ag, g_csr_ag);
    cudaGetSymbolAddress((void**)&pcsr_d, g_csr_d);

    const int* eab_src = e_ab;           const int* eab_dst = e_ab + EAB;
    const int* eag_src = e_ag;           const int* eag_dst = e_ag + EAG;
    const int* ed_src  = e_d;            const int* ed_dst  = e_d + ED;

    // ---- CSR build: ab + ag graphs ----
    k_filli<<<(NTOT + 255) / 256, 256>>>(pdegi, 0, NTOT);
    k_deg<<<(EAB + 255) / 256, 256>>>(eab_dst, EAB, pdegi);
    k_deg<<<(EAG + 255) / 256, 256>>>(eag_dst, EAG, pdegi + NAB);
    k_dinv<<<(NTOT + 255) / 256, 256>>>(pdegi, pdinv, NTOT);
    k_scan<<<1, 1024>>>(pdegi, poff_ab, NAB);
    k_scan<<<1, 1024>>>(pdegi + NAB, poff_ag, NAG);
    k_copyi<<<(NAB + 255) / 256, 256>>>(poff_ab, pcur, NAB);
    k_copyi<<<(NAG + 255) / 256, 256>>>(poff_ag, pcur + NAB, NAG);
    k_scatter<<<(EAB + 255) / 256, 256>>>(eab_src, eab_dst, EAB, pcur, pcsr_ab, 0);
    k_scatter<<<(EAG + 255) / 256, 256>>>(eag_src, eag_dst, EAG, pcur, pcsr_ag, NAB);
    // ---- CSR build: d graph ----
    k_filli<<<(NTOT + 255) / 256, 256>>>(pdegi, 0, NTOT);
    k_deg<<<(ED + 255) / 256, 256>>>(ed_dst, ED, pdegi);
    k_scan<<<1, 1024>>>(pdegi, poff_d, NTOT);
    k_copyi<<<(NTOT + 255) / 256, 256>>>(poff_d, pcur, NTOT);
    k_scatter<<<(ED + 255) / 256, 256>>>(ed_src, ed_dst, ED, pcur, pcsr_d, 0);

    // ---- GCN GEMMs: h into g_B ----
    {
        dim3 gab((NAB + 127) / 128, 2);
        k_gemm256<false><<<gab, 256>>>(x_ab, W_gcn, pB, NAB);
        k_gemm256<false><<<gab, 256>>>(x_ag, W_aggcn, pB + (size_t)NAB * FF, NAB);
    }
    // ---- GCN aggregate (gather) into g_A ----
    k_gcn_gather<<<(NAB * 32 + 255) / 256, 256>>>(poff_ab, pcsr_ab, pB, pA, pdinv, b_gcn, NAB);
    k_gcn_gather<<<(NAG * 32 + 255) / 256, 256>>>(poff_ag, pcsr_ag,
                 pB + (size_t)NAB * FF, pA + (size_t)NAB * FF, pdinv + NAB, b_aggcn, NAG);

    // ---- BN1 + relu -> g_X ----
    k_fill<<<4, 256>>>(psum, 0.f, 1024);
    k_fill<<<4, 256>>>(psq, 0.f, 1024);
    k_stats<<<96, 256>>>(pA, NAB, psum, psq);
    k_stats<<<96, 256>>>(pA + (size_t)NAB * FF, NAB, psum + 256, psq + 256);
    k_finalize<<<4, 256>>>(psum, psq, pmu, prstd, NAB, 512);
    k_bnrelu<<<((size_t)NAB * FF + 255) / 256, 256>>>(pA, pX, pmu, prstd, g1, be1, NAB);
    k_bnrelu<<<((size_t)NAB * FF + 255) / 256, 256>>>(pA + (size_t)NAB * FF,
                 pX + (size_t)NAB * FF, pmu + 256, prstd + 256, ag_g1, ag_be1, NAB);

    // ---- GAT1: g_X -> g_A ; GAT2: relu(g_A) -> g_A ----
    gat_layer(pX, false, W_gat,  a_src,  a_dst,  b_gat,  pB, pA, poff_d, pcsr_d, phs, phd);
    gat_layer(pA, true,  W_gat2, a_src2, a_dst2, b_gat2, pB, pA, poff_d, pcsr_d, phs, phd);

    // ---- final BN stats over concat halves ----
    k_fill<<<4, 256>>>(psum, 0.f, 1024);
    k_fill<<<4, 256>>>(psq, 0.f, 1024);
    k_stats<<<96, 256>>>(pA, NAB, psum, psq);                                  // x1
    k_stats<<<96, 256>>>(pX, NAB, psum + 256, psq + 256);                      // h_ab
    k_stats<<<96, 256>>>(pA + (size_t)NAB * FF, NAG, psum + 512, psq + 512);   // x2
    k_stats<<<96, 256>>>(pX + (size_t)NAB * FF, NAG, psum + 768, psq + 768);   // h_ag
    k_finalize<<<4, 256>>>(psum, psq, pmu, prstd, NAB, 1024);

    // ---- final outputs ----
    k_final<<<(NAB * 32 + 255) / 256, 256>>>(pA, pX, pmu, prstd, g2, be2, W_fc, b_fc,
                                             out, NAB);
    k_final<<<(NAG * 32 + 255) / 256, 256>>>(pA + (size_t)NAB * FF, pX + (size_t)NAB * FF,
                                             pmu + 512, prstd + 512, ag_g2, ag_be2,
                                             W_agfc, b_agfc, out + NAB, NAG);
}

// round 7
// speedup vs baseline: 1.3111x; 1.1766x over previous
#include <cuda_runtime.h>
#include <cstdint>

// ---------------- problem constants ----------------
constexpr int NAB  = 20000;
constexpr int NAG  = 20000;
constexpr int NTOT = NAB + NAG;      // 40000
constexpr int FF   = 256;
constexpr int EAB  = 320000;
constexpr int EAG  = 320000;
constexpr int ED   = 640000;
constexpr float EPS = 1e-5f;
constexpr float SLOPE = 0.2f;
constexpr float NINF = -3.0e38f;

// ---------------- scratch (device globals, no allocs) ----------------
__device__ float g_X[(size_t)NTOT * FF];
__device__ float g_A[(size_t)NTOT * FF];
__device__ float g_B[(size_t)NTOT * FF];
__device__ float g_dinv[NTOT];
__device__ float g_hs[NTOT], g_hd[NTOT];
__device__ float g_sum[1024], g_sq[1024], g_mu[1024], g_rstd[1024];

__device__ int g_degi[NTOT];
__device__ int g_cur[NTOT];
__device__ int g_off_ab[NAB + 1];
__device__ int g_off_ag[NAG + 1];
__device__ int g_off_d[NTOT + 1];
__device__ int g_csr_ab[EAB];
__device__ int g_csr_ag[EAG];
__device__ int g_csr_d[ED];

// ---------------- f32x2 helpers (sm_103a packed fp32 FMA) ----------------
typedef unsigned long long u64t;
__device__ __forceinline__ void fma2(u64t& d, u64t a, u64t b, u64t c) {
    asm("fma.rn.f32x2 %0, %1, %2, %3;" : "=l"(d) : "l"(a), "l"(b), "l"(c));
}
__device__ __forceinline__ u64t packf2(float lo, float hi) {
    u64t d;
    asm("mov.b64 %0, {%1, %2};" : "=l"(d) : "r"(__float_as_uint(lo)), "r"(__float_as_uint(hi)));
    return d;
}
__device__ __forceinline__ void unpackf2(float& lo, float& hi, u64t v) {
    unsigned int l, h;
    asm("mov.b64 {%0, %1}, %2;" : "=r"(l), "=r"(h) : "l"(v));
    lo = __uint_as_float(l); hi = __uint_as_float(h);
}

__device__ __forceinline__ float lrelu(float x) { return x > 0.f ? x : SLOPE * x; }

// ---------------- tiny utility kernels ----------------
__global__ void k_filli(int* p, int v, int n) {
    int i = blockIdx.x * blockDim.x + threadIdx.x;
    if (i < n) p[i] = v;
}
__global__ void k_fill(float* p, float v, int n) {
    int i = blockIdx.x * blockDim.x + threadIdx.x;
    if (i < n) p[i] = v;
}
__global__ void k_copyi(const int* __restrict__ a, int* __restrict__ b, int n) {
    int i = blockIdx.x * blockDim.x + threadIdx.x;
    if (i < n) b[i] = a[i];
}
__global__ void k_deg(const int* __restrict__ dst, int E, int* __restrict__ deg) {
    int i = blockIdx.x * blockDim.x + threadIdx.x;
    if (i < E) atomicAdd(&deg[dst[i]], 1);
}
__global__ void k_dinv(const int* __restrict__ deg, float* __restrict__ dinv, int n) {
    int i = blockIdx.x * blockDim.x + threadIdx.x;
    if (i < n) dinv[i] = rsqrtf((float)deg[i] + 1.0f);
}

// single-block exclusive scan (int4-vectorized sums)
__global__ void __launch_bounds__(1024) k_scan(const int* __restrict__ deg,
                                               int* __restrict__ off, int n) {
    __shared__ int ssum[1024];
    int t = threadIdx.x;
    int C = (((n + 1023) / 1024) + 3) & ~3;   // multiple of 4
    int lo = min(t * C, n), hi = min(lo + C, n);
    int s = 0;
    int i = lo;
    for (; i + 4 <= hi; i += 4) {
        int4 v = *(const int4*)(deg + i);
        s += v.x + v.y + v.z + v.w;
    }
    for (; i < hi; i++) s += deg[i];
    ssum[t] = s;
    __syncthreads();
    for (int d = 1; d < 1024; d <<= 1) {
        int v = (t >= d) ? ssum[t - d] : 0;
        __syncthreads();
        if (t >= d) ssum[t] += v;
        __syncthreads();
    }
    int run = (t > 0) ? ssum[t - 1] : 0;
    for (int j = lo; j < hi; j++) { off[j] = run; run += deg[j]; }
    if (t == 0) off[n] = ssum[1023];
}

__global__ void k_scatter(const int* __restrict__ src, const int* __restrict__ dst, int E,
                          int* __restrict__ cur, int* __restrict__ csr, int dstbase) {
    int i = blockIdx.x * blockDim.x + threadIdx.x;
    if (i >= E) return;
    int pos = atomicAdd(&cur[dst[i] + dstbase], 1);
    csr[pos] = src[i];
}

// ---------------- f32x2 SGEMM: C[M,256] = (relu?)A[M,256] @ W[256,256] ----------------
// SCORES: also atomically accumulate hs[r]+=C_row.a_s, hd[r]+=C_row.a_d
template<bool RELU, bool SCORES>
__global__ void __launch_bounds__(256) k_gemm256(const float* __restrict__ A,
                                                 const float* __restrict__ W,
                                                 float* __restrict__ C, int M,
                                                 const float* __restrict__ a_s,
                                                 const float* __restrict__ a_d,
                                                 float* __restrict__ hs,
                                                 float* __restrict__ hd) {
    __shared__ float As[16][128];
    __shared__ float Bs[16][128];
    const int tid = threadIdx.x;
    const int m0 = blockIdx.x * 128;
    const int n0 = blockIdx.y * 128;
    const int tx = tid & 15, ty = tid >> 4;

    const int arow = tid >> 2;
    const int acol = (tid & 3) * 4;
    const int brow = tid >> 5;
    const int bcol = (tid & 31) * 4;

    u64t acc[8][4];
#pragma unroll
    for (int i = 0; i < 8; i++)
#pragma unroll
        for (int j = 0; j < 4; j++) acc[i][j] = 0ull;

    for (int k0 = 0; k0 < 256; k0 += 16) {
#pragma unroll
        for (int i = 0; i < 2; i++) {
            int r = m0 + arow + i * 64;
            int rc = r < M ? r : M - 1;
            float4 v = *(const float4*)(A + (size_t)rc * FF + k0 + acol);
            if (RELU) {
                v.x = fmaxf(v.x, 0.f); v.y = fmaxf(v.y, 0.f);
                v.z = fmaxf(v.z, 0.f); v.w = fmaxf(v.w, 0.f);
            }
            As[acol + 0][arow + i * 64] = v.x;
            As[acol + 1][arow + i * 64] = v.y;
            As[acol + 2][arow + i * 64] = v.z;
            As[acol + 3][arow + i * 64] = v.w;
        }
#pragma unroll
        for (int i = 0; i < 2; i++) {
            int kr = brow + i * 8;
            float4 v = *(const float4*)(W + (size_t)(k0 + kr) * FF + n0 + bcol);
            *(float4*)&Bs[kr][bcol] = v;
        }
        __syncthreads();
#pragma unroll
        for (int kk = 0; kk < 16; kk++) {
            float4 av0 = *(const float4*)&As[kk][ty * 8];
            float4 av1 = *(const float4*)&As[kk][ty * 8 + 4];
            float4 bv0 = *(const float4*)&Bs[kk][tx * 8];
            float4 bv1 = *(const float4*)&Bs[kk][tx * 8 + 4];
            u64t bp[4];
            bp[0] = packf2(bv0.x, bv0.y);
            bp[1] = packf2(bv0.z, bv0.w);
            bp[2] = packf2(bv1.x, bv1.y);
            bp[3] = packf2(bv1.z, bv1.w);
            u64t ap[8];
            ap[0] = packf2(av0.x, av0.x);
            ap[1] = packf2(av0.y, av0.y);
            ap[2] = packf2(av0.z, av0.z);
            ap[3] = packf2(av0.w, av0.w);
            ap[4] = packf2(av1.x, av1.x);
            ap[5] = packf2(av1.y, av1.y);
            ap[6] = packf2(av1.z, av1.z);
            ap[7] = packf2(av1.w, av1.w);
#pragma unroll
            for (int i = 0; i < 8; i++)
#pragma unroll
                for (int j = 0; j < 4; j++) fma2(acc[i][j], ap[i], bp[j], acc[i][j]);
        }
        __syncthreads();
    }

    float as0[8], ad0[8];
    if (SCORES) {
#pragma unroll
        for (int j = 0; j < 4; j++) {
            as0[j] = __ldg(a_s + n0 + tx * 8 + j);
            as0[j + 4] = __ldg(a_s + n0 + tx * 8 + 4 + j);
            ad0[j] = __ldg(a_d + n0 + tx * 8 + j);
            ad0[j + 4] = __ldg(a_d + n0 + tx * 8 + 4 + j);
        }
    }

#pragma unroll
    for (int i = 0; i < 8; i++) {
        int r = m0 + ty * 8 + i;
        float v[8];
        unpackf2(v[0], v[1], acc[i][0]);
        unpackf2(v[2], v[3], acc[i][1]);
        unpackf2(v[4], v[5], acc[i][2]);
        unpackf2(v[6], v[7], acc[i][3]);
        if (r < M) {
            *(float4*)(C + (size_t)r * FF + n0 + tx * 8)     = make_float4(v[0], v[1], v[2], v[3]);
            *(float4*)(C + (size_t)r * FF + n0 + tx * 8 + 4) = make_float4(v[4], v[5], v[6], v[7]);
        }
        if (SCORES) {
            float ps = 0.f, pd = 0.f;
#pragma unroll
            for (int j = 0; j < 8; j++) { ps += v[j] * as0[j]; pd += v[j] * ad0[j]; }
#pragma unroll
            for (int o = 8; o > 0; o >>= 1) {           // reduce over 16 tx lanes
                ps += __shfl_xor_sync(0xffffffffu, ps, o);
                pd += __shfl_xor_sync(0xffffffffu, pd, o);
            }
            if ((tid & 15) == 0 && r < M) {
                atomicAdd(hs + r, ps);
                atomicAdd(hd + r, pd);
            }
        }
    }
}

// ---------------- GCN gather: warp per node ----------------
__global__ void k_gcn_gather(const int* __restrict__ off, const int* __restrict__ csr,
                             const float* __restrict__ h, float* __restrict__ out,
                             const float* __restrict__ dinv, const float* __restrict__ b,
                             int n) {
    int w = (blockIdx.x * blockDim.x + threadIdx.x) >> 5;
    int lane = threadIdx.x & 31;
    if (w >= n) return;
    int e0 = off[w], e1 = off[w + 1];
    float dv = dinv[w];
    float4 a0 = make_float4(0.f, 0.f, 0.f, 0.f);
    float4 a1 = make_float4(0.f, 0.f, 0.f, 0.f);
    for (int base = e0; base < e1; base += 32) {
        int e = base + lane;
        int idx = (e < e1) ? csr[e] : 0;
        float wv = (e < e1) ? dinv[idx] : 0.f;
        int cnt = min(32, e1 - base);
        for (int k = 0; k < cnt; k++) {
            int s = __shfl_sync(0xffffffffu, idx, k);
            float ws = __shfl_sync(0xffffffffu, wv, k);
            const float4* hp = (const float4*)(h + (size_t)s * FF) + lane;
            float4 v0 = hp[0];
            float4 v1 = hp[32];
            a0.x += v0.x * ws; a0.y += v0.y * ws; a0.z += v0.z * ws; a0.w += v0.w * ws;
            a1.x += v1.x * ws; a1.y += v1.y * ws; a1.z += v1.z * ws; a1.w += v1.w * ws;
        }
    }
    {
        const float4* hp = (const float4*)(h + (size_t)w * FF) + lane;
        float4 v0 = hp[0], v1 = hp[32];
        a0.x += v0.x * dv; a0.y += v0.y * dv; a0.z += v0.z * dv; a0.w += v0.w * dv;
        a1.x += v1.x * dv; a1.y += v1.y * dv; a1.z += v1.z * dv; a1.w += v1.w * dv;
    }
    float4 b0 = *((const float4*)b + lane);
    float4 b1 = *((const float4*)b + lane + 32);
    float4 o0 = make_float4(a0.x * dv + b0.x, a0.y * dv + b0.y, a0.z * dv + b0.z, a0.w * dv + b0.w);
    float4 o1 = make_float4(a1.x * dv + b1.x, a1.y * dv + b1.y, a1.z * dv + b1.z, a1.w * dv + b1.w);
    float4* op = (float4*)(out + (size_t)w * FF) + lane;
    op[0] = o0;
    op[32] = o1;
}

// ---------------- BN ----------------
__global__ void k_stats(const float* __restrict__ X, int nrows,
                        float* __restrict__ sum, float* __restrict__ sq) {
    int c = threadIdx.x;
    float s = 0.f, q = 0.f;
    for (int r = blockIdx.x; r < nrows; r += gridDim.x) {
        float v = X[(size_t)r * FF + c];
        s += v; q += v * v;
    }
    atomicAdd(&sum[c], s);
    atomicAdd(&sq[c], q);
}

__global__ void k_finalize(const float* __restrict__ sum, const float* __restrict__ sq,
                           float* __restrict__ mu, float* __restrict__ rstd, int n, int cnt) {
    int i = blockIdx.x * blockDim.x + threadIdx.x;
    if (i >= cnt) return;
    float m = sum[i] / n;
    mu[i] = m;
    rstd[i] = rsqrtf(sq[i] / n - m * m + EPS);
}

__global__ void k_bnrelu(const float* __restrict__ X, float* __restrict__ Y,
                         const float* __restrict__ mu, const float* __restrict__ rstd,
                         const float* __restrict__ g, const float* __restrict__ b, int n) {
    int idx = blockIdx.x * blockDim.x + threadIdx.x;
    if (idx >= n * FF) return;
    int c = idx & 255;
    float v = (X[idx] - mu[c]) * rstd[c] * g[c] + b[c];
    Y[idx] = fmaxf(v, 0.f);
}

// ---------------- fused GAT per node ----------------
__global__ void k_gat_node(const int* __restrict__ off, const int* __restrict__ csr,
                           const float* __restrict__ h, float* __restrict__ out,
                           const float* __restrict__ hs, const float* __restrict__ hd,
                           const float* __restrict__ b, int n) {
    int w = (blockIdx.x * blockDim.x + threadIdx.x) >> 5;
    int lane = threadIdx.x & 31;
    if (w >= n) return;
    int e0 = off[w], e1 = off[w + 1];
    float hdn = hd[w];
    float self_e = lrelu(hs[w] + hdn);

    float m = (lane == 0) ? self_e : NINF;
    float s = (lane == 0) ? 1.f : 0.f;
    for (int e = e0 + lane; e < e1; e += 32) {
        float v = lrelu(hs[csr[e]] + hdn);
        if (v > m) { s = s * __expf(m - v) + 1.f; m = v; }
        else       { s += __expf(v - m); }
    }
#pragma unroll
    for (int o = 16; o > 0; o >>= 1) {
        float mo = __shfl_xor_sync(0xffffffffu, m, o);
        float so = __shfl_xor_sync(0xffffffffu, s, o);
        float mn = fmaxf(m, mo);
        s = s * __expf(m - mn) + so * __expf(mo - mn);
        m = mn;
    }
    float inv = 1.f / s;

    float4 a0, a1;
    {
        float sa = __expf(self_e - m) * inv;
        const float4* hp = (const float4*)(h + (size_t)w * FF) + lane;
        float4 v0 = hp[0], v1 = hp[32];
        a0 = make_float4(v0.x * sa, v0.y * sa, v0.z * sa, v0.w * sa);
        a1 = make_float4(v1.x * sa, v1.y * sa, v1.z * sa, v1.w * sa);
    }
    for (int base = e0; base < e1; base += 32) {
        int e = base + lane;
        int idx = (e < e1) ? csr[e] : 0;
        float al = 0.f;
        if (e < e1) al = __expf(lrelu(hs[idx] + hdn) - m) * inv;
        int cnt = min(32, e1 - base);
        for (int k = 0; k < cnt; k++) {
            int sn = __shfl_sync(0xffffffffu, idx, k);
            float av = __shfl_sync(0xffffffffu, al, k);
            const float4* hp = (const float4*)(h + (size_t)sn * FF) + lane;
            float4 v0 = hp[0];
            float4 v1 = hp[32];
            a0.x += v0.x * av; a0.y += v0.y * av; a0.z += v0.z * av; a0.w += v0.w * av;
            a1.x += v1.x * av; a1.y += v1.y * av; a1.z += v1.z * av; a1.w += v1.w * av;
        }
    }
    float4 b0 = *((const float4*)b + lane);
    float4 b1 = *((const float4*)b + lane + 32);
    a0.x += b0.x; a0.y += b0.y; a0.z += b0.z; a0.w += b0.w;
    a1.x += b1.x; a1.y += b1.y; a1.z += b1.z; a1.w += b1.w;
    float4* op = (float4*)(out + (size_t)w * FF) + lane;
    op[0] = a0;
    op[32] = a1;
}

// ---------------- final: relu(bn(concat[X,H])) @ Wfc + bfc ----------------
__global__ void k_final(const float* __restrict__ Xp, const float* __restrict__ Hp,
                        const float* __restrict__ mu, const float* __restrict__ rstd,
                        const float* __restrict__ g, const float* __restrict__ b,
                        const float* __restrict__ Wfc, const float* __restrict__ bfc,
                        float* __restrict__ out, int n) {
    int w = (blockIdx.x * blockDim.x + threadIdx.x) >> 5;
    int lane = threadIdx.x & 31;
    if (w >= n) return;
    float acc = 0.f;
#pragma unroll
    for (int j = 0; j < 16; j++) {
        int c = j * 32 + lane;
        float v = (c < FF) ? Xp[(size_t)w * FF + c] : Hp[(size_t)w * FF + (c - FF)];
        v = (v - mu[c]) * rstd[c] * g[c] + b[c];
        v = fmaxf(v, 0.f);
        acc += v * __ldg(Wfc + c);
    }
#pragma unroll
    for (int off = 16; off > 0; off >>= 1) acc += __shfl_down_sync(0xffffffffu, acc, off);
    if (lane == 0) out[w] = acc + bfc[0];
}

// ---------------- host orchestration ----------------
static void gat_layer(const float* xin, bool relu_in, const float* W, const float* a_s,
                      const float* a_d, const float* b, float* hbuf, float* outbuf,
                      const int* off, const int* csr,
                      float* hs, float* hd) {
    k_fill<<<(NTOT + 255) / 256, 256>>>(hs, 0.f, NTOT);
    k_fill<<<(NTOT + 255) / 256, 256>>>(hd, 0.f, NTOT);
    dim3 gg((NTOT + 127) / 128, 2);
    if (relu_in) k_gemm256<true,  true><<<gg, 256>>>(xin, W, hbuf, NTOT, a_s, a_d, hs, hd);
    else         k_gemm256<false, true><<<gg, 256>>>(xin, W, hbuf, NTOT, a_s, a_d, hs, hd);
    k_gat_node<<<(NTOT * 32 + 255) / 256, 256>>>(off, csr, hbuf, outbuf, hs, hd, b, NTOT);
}

extern "C" void kernel_launch(void* const* d_in, const int* in_sizes, int n_in,
                              void* d_out, int out_size) {
    const float* x_ab   = (const float*)d_in[0];
    const float* x_ag   = (const float*)d_in[1];
    const float* W_gcn  = (const float*)d_in[2];
    const float* b_gcn  = (const float*)d_in[3];
    const float* g1     = (const float*)d_in[4];
    const float* be1    = (const float*)d_in[5];
    const float* W_aggcn= (const float*)d_in[6];
    const float* b_aggcn= (const float*)d_in[7];
    const float* ag_g1  = (const float*)d_in[8];
    const float* ag_be1 = (const float*)d_in[9];
    const float* W_gat  = (const float*)d_in[10];
    const float* a_src  = (const float*)d_in[11];
    const float* a_dst  = (const float*)d_in[12];
    const float* b_gat  = (const float*)d_in[13];
    const float* W_gat2 = (const float*)d_in[14];
    const float* a_src2 = (const float*)d_in[15];
    const float* a_dst2 = (const float*)d_in[16];
    const float* b_gat2 = (const float*)d_in[17];
    const float* ag_g2  = (const float*)d_in[18];
    const float* ag_be2 = (const float*)d_in[19];
    const float* W_agfc = (const float*)d_in[20];
    const float* b_agfc = (const float*)d_in[21];
    const float* g2     = (const float*)d_in[22];
    const float* be2    = (const float*)d_in[23];
    const float* W_fc   = (const float*)d_in[24];
    const float* b_fc   = (const float*)d_in[25];
    const int* e_ab     = (const int*)d_in[26];
    const int* e_ag     = (const int*)d_in[27];
    const int* e_d      = (const int*)d_in[28];
    float* out = (float*)d_out;

    float *pX, *pA, *pB, *pdinv, *phs, *phd, *psum, *psq, *pmu, *prstd;
    int *pdegi, *pcur, *poff_ab, *poff_ag, *poff_d, *pcsr_ab, *pcsr_ag, *pcsr_d;
    cudaGetSymbolAddress((void**)&pX, g_X);
    cudaGetSymbolAddress((void**)&pA, g_A);
    cudaGetSymbolAddress((void**)&pB, g_B);
    cudaGetSymbolAddress((void**)&pdinv, g_dinv);
    cudaGetSymbolAddress((void**)&phs, g_hs);
    cudaGetSymbolAddress((void**)&phd, g_hd);
    cudaGetSymbolAddress((void**)&psum, g_sum);
    cudaGetSymbolAddress((void**)&psq, g_sq);
    cudaGetSymbolAddress((void**)&pmu, g_mu);
    cudaGetSymbolAddress((void**)&prstd, g_rstd);
    cudaGetSymbolAddress((void**)&pdegi, g_degi);
    cudaGetSymbolAddress((void**)&pcur, g_cur);
    cudaGetSymbolAddress((void**)&poff_ab, g_off_ab);
    cudaGetSymbolAddress((void**)&poff_ag, g_off_ag);
    cudaGetSymbolAddress((void**)&poff_d, g_off_d);
    cudaGetSymbolAddress((void**)&pcsr_ab, g_csr_ab);
    cudaGetSymbolAddress((void**)&pcsr_ag, g_csr_ag);
    cudaGetSymbolAddress((void**)&pcsr_d, g_csr_d);

    const int* eab_src = e_ab;           const int* eab_dst = e_ab + EAB;
    const int* eag_src = e_ag;           const int* eag_dst = e_ag + EAG;
    const int* ed_src  = e_d;            const int* ed_dst  = e_d + ED;

    // ---- CSR build (launch order arranged so launch #5 = first GEMM, for ncu -s 5) ----
    k_filli<<<(NTOT + 255) / 256, 256>>>(pdegi, 0, NTOT);                       // 0
    k_deg<<<(EAB + 255) / 256, 256>>>(eab_dst, EAB, pdegi);                     // 1
    k_deg<<<(EAG + 255) / 256, 256>>>(eag_dst, EAG, pdegi + NAB);               // 2
    k_dinv<<<(NTOT + 255) / 256, 256>>>(pdegi, pdinv, NTOT);                    // 3
    k_scan<<<1, 1024>>>(pdegi, poff_ab, NAB);                                   // 4
    {
        dim3 gab((NAB + 127) / 128, 2);
        k_gemm256<false, false><<<gab, 256>>>(x_ab, W_gcn, pB, NAB,
                                              nullptr, nullptr, nullptr, nullptr);   // 5 (profiled)
        k_gemm256<false, false><<<gab, 256>>>(x_ag, W_aggcn, pB + (size_t)NAB * FF, NAB,
                                              nullptr, nullptr, nullptr, nullptr);
    }
    k_scan<<<1, 1024>>>(pdegi + NAB, poff_ag, NAG);
    k_copyi<<<(NAB + 255) / 256, 256>>>(poff_ab, pcur, NAB);
    k_copyi<<<(NAG + 255) / 256, 256>>>(poff_ag, pcur + NAB, NAG);
    k_scatter<<<(EAB + 255) / 256, 256>>>(eab_src, eab_dst, EAB, pcur, pcsr_ab, 0);
    k_scatter<<<(EAG + 255) / 256, 256>>>(eag_src, eag_dst, EAG, pcur, pcsr_ag, NAB);

    // ---- GCN aggregate (gather) into g_A ----
    k_gcn_gather<<<(NAB * 32 + 255) / 256, 256>>>(poff_ab, pcsr_ab, pB, pA, pdinv, b_gcn, NAB);
    k_gcn_gather<<<(NAG * 32 + 255) / 256, 256>>>(poff_ag, pcsr_ag,
                 pB + (size_t)NAB * FF, pA + (size_t)NAB * FF, pdinv + NAB, b_aggcn, NAG);

    // ---- CSR build: d graph ----
    k_filli<<<(NTOT + 255) / 256, 256>>>(pdegi, 0, NTOT);
    k_deg<<<(ED + 255) / 256, 256>>>(ed_dst, ED, pdegi);
    k_scan<<<1, 1024>>>(pdegi, poff_d, NTOT);
    k_copyi<<<(NTOT + 255) / 256, 256>>>(poff_d, pcur, NTOT);
    k_scatter<<<(ED + 255) / 256, 256>>>(ed_src, ed_dst, ED, pcur, pcsr_d, 0);

    // ---- BN1 + relu -> g_X ----
    k_fill<<<4, 256>>>(psum, 0.f, 1024);
    k_fill<<<4, 256>>>(psq, 0.f, 1024);
    k_stats<<<148, 256>>>(pA, NAB, psum, psq);
    k_stats<<<148, 256>>>(pA + (size_t)NAB * FF, NAB, psum + 256, psq + 256);
    k_finalize<<<4, 256>>>(psum, psq, pmu, prstd, NAB, 512);
    k_bnrelu<<<((size_t)NAB * FF + 255) / 256, 256>>>(pA, pX, pmu, prstd, g1, be1, NAB);
    k_bnrelu<<<((size_t)NAB * FF + 255) / 256, 256>>>(pA + (size_t)NAB * FF,
                 pX + (size_t)NAB * FF, pmu + 256, prstd + 256, ag_g1, ag_be1, NAB);

    // ---- GAT1: g_X -> g_A ; GAT2: relu(g_A) -> g_A ----
    gat_layer(pX, false, W_gat,  a_src,  a_dst,  b_gat,  pB, pA, poff_d, pcsr_d, phs, phd);
    gat_layer(pA, true,  W_gat2, a_src2, a_dst2, b_gat2, pB, pA, poff_d, pcsr_d, phs, phd);

    // ---- final BN stats over concat halves ----
    k_fill<<<4, 256>>>(psum, 0.f, 1024);
    k_fill<<<4, 256>>>(psq, 0.f, 1024);
    k_stats<<<148, 256>>>(pA, NAB, psum, psq);                                  // x1
    k_stats<<<148, 256>>>(pX, NAB, psum + 256, psq + 256);                      // h_ab
    k_stats<<<148, 256>>>(pA + (size_t)NAB * FF, NAG, psum + 512, psq + 512);   // x2
    k_stats<<<148, 256>>>(pX + (size_t)NAB * FF, NAG, psum + 768, psq + 768);   // h_ag
    k_finalize<<<4, 256>>>(psum, psq, pmu, prstd, NAB, 1024);

    // ---- final outputs ----
    k_final<<<(NAB * 32 + 255) / 256, 256>>>(pA, pX, pmu, prstd, g2, be2, W_fc, b_fc,
                                             out, NAB);
    k_final<<<(NAG * 32 + 255) / 256, 256>>>(pA + (size_t)NAB * FF, pX + (size_t)NAB * FF,
                                             pmu + 512, prstd + 512, ag_g2, ag_be2,
                                             W_agfc, b_agfc, out + NAB, NAG);
}

// round 8
// speedup vs baseline: 1.5980x; 1.2189x over previous
#include <cuda_runtime.h>
#include <cstdint>

// ---------------- problem constants ----------------
constexpr int NAB  = 20000;
constexpr int NAG  = 20000;
constexpr int NTOT = NAB + NAG;      // 40000
constexpr int FF   = 256;
constexpr int EAB  = 320000;
constexpr int EAG  = 320000;
constexpr int ED   = 640000;
constexpr float EPS = 1e-5f;
constexpr float SLOPE = 0.2f;
constexpr float NINF = -3.0e38f;

// ---------------- scratch (device globals, no allocs) ----------------
__device__ float g_X[(size_t)NTOT * FF];
__device__ float g_A[(size_t)NTOT * FF];
__device__ float g_B[(size_t)NTOT * FF];
__device__ float g_dinv[NTOT];
__device__ float g_sc[2 * NTOT];            // hs | hd
__device__ float g_sumsq[2048];             // sum[1024] | sq[1024]
__device__ float g_mu[1024], g_rstd[1024];

__device__ int g_degi[NTOT];
__device__ int g_cur[NTOT];
__device__ int g_off_g[NTOT + 1];           // combined GCN CSR offsets
__device__ int g_off_d[NTOT + 1];
__device__ int g_csr_g[EAB + EAG];
__device__ int g_csr_d[ED];
__device__ int g_partials[64];

// ---------------- f32x2 helpers (sm_103a packed fp32 FMA) ----------------
typedef unsigned long long u64t;
__device__ __forceinline__ void fma2(u64t& d, u64t a, u64t b, u64t c) {
    asm("fma.rn.f32x2 %0, %1, %2, %3;" : "=l"(d) : "l"(a), "l"(b), "l"(c));
}
__device__ __forceinline__ u64t packf2(float lo, float hi) {
    u64t d;
    asm("mov.b64 %0, {%1, %2};" : "=l"(d) : "r"(__float_as_uint(lo)), "r"(__float_as_uint(hi)));
    return d;
}
__device__ __forceinline__ void unpackf2(float& lo, float& hi, u64t v) {
    unsigned int l, h;
    asm("mov.b64 {%0, %1}, %2;" : "=r"(l), "=r"(h) : "l"(v));
    lo = __uint_as_float(l); hi = __uint_as_float(h);
}

__device__ __forceinline__ float lrelu(float x) { return x > 0.f ? x : SLOPE * x; }

// ---------------- tiny utility kernels ----------------
__global__ void k_filli(int* p, int v, int n) {
    int i = blockIdx.x * blockDim.x + threadIdx.x;
    if (i < n) p[i] = v;
}
__global__ void k_fill(float* p, float v, int n) {
    int i = blockIdx.x * blockDim.x + threadIdx.x;
    if (i < n) p[i] = v;
}
__global__ void k_copyi(const int* __restrict__ a, int* __restrict__ b, int n) {
    int i = blockIdx.x * blockDim.x + threadIdx.x;
    if (i < n) b[i] = a[i];
}
__global__ void k_deg(const int* __restrict__ dst, int E, int* __restrict__ deg) {
    int i = blockIdx.x * blockDim.x + threadIdx.x;
    if (i < E) atomicAdd(&deg[dst[i]], 1);
}
__global__ void k_dinv(const int* __restrict__ deg, float* __restrict__ dinv, int n) {
    int i = blockIdx.x * blockDim.x + threadIdx.x;
    if (i < n) dinv[i] = rsqrtf((float)deg[i] + 1.0f);
}

// ---------------- parallel exclusive scan (3 kernels) ----------------
constexpr int SCAN_T = 256;
constexpr int SCAN_ITEMS = 4;
constexpr int SCAN_CHUNK = SCAN_T * SCAN_ITEMS;   // 1024

__global__ void k_scan1(const int* __restrict__ deg, int n, int* __restrict__ partials) {
    __shared__ int sh[SCAN_T];
    int b = blockIdx.x, t = threadIdx.x;
    int base = b * SCAN_CHUNK + t * SCAN_ITEMS;
    int s = 0;
#pragma unroll
    for (int k = 0; k < SCAN_ITEMS; k++) { int i = base + k; if (i < n) s += deg[i]; }
    sh[t] = s;
    __syncthreads();
    for (int d = 128; d > 0; d >>= 1) {
        if (t < d) sh[t] += sh[t + d];
        __syncthreads();
    }
    if (t == 0) partials[b] = sh[0];
}

__global__ void k_scan2(int* __restrict__ partials, int nb, int* __restrict__ off, int n) {
    __shared__ int sh[64];
    int t = threadIdx.x;
    int v = (t < nb) ? partials[t] : 0;
    sh[t] = v;
    __syncthreads();
    for (int d = 1; d < 64; d <<= 1) {
        int u = (t >= d) ? sh[t - d] : 0;
        __syncthreads();
        sh[t] += u;
        __syncthreads();
    }
    if (t < nb) partials[t] = sh[t] - v;    // exclusive prefix
    if (t == 0) off[n] = sh[63];            // grand total
}

__global__ void k_scan3(const int* __restrict__ deg, int n,
                        const int* __restrict__ partials, int* __restrict__ off) {
    __shared__ int sh[SCAN_T];
    int b = blockIdx.x, t = threadIdx.x;
    int base = b * SCAN_CHUNK + t * SCAN_ITEMS;
    int v[SCAN_ITEMS];
    int s = 0;
#pragma unroll
    for (int k = 0; k < SCAN_ITEMS; k++) { int i = base + k; v[k] = (i < n) ? deg[i] : 0; s += v[k]; }
    sh[t] = s;
    __syncthreads();
    for (int d = 1; d < SCAN_T; d <<= 1) {
        int u = (t >= d) ? sh[t - d] : 0;
        __syncthreads();
        sh[t] += u;
        __syncthreads();
    }
    int run = partials[b] + sh[t] - s;
#pragma unroll
    for (int k = 0; k < SCAN_ITEMS; k++) {
        int i = base + k;
        if (i < n) { off[i] = run; run += v[k]; }
    }
}

__global__ void k_scatter(const int* __restrict__ src, const int* __restrict__ dst, int E,
                          int* __restrict__ cur, int* __restrict__ csr,
                          int dstbase, int srcbase) {
    int i = blockIdx.x * blockDim.x + threadIdx.x;
    if (i >= E) return;
    int pos = atomicAdd(&cur[dst[i] + dstbase], 1);
    csr[pos] = src[i] + srcbase;
}

// ---------------- f32x2 SGEMM (double-buffered) ----------------
__device__ __forceinline__ void gemm_load_tile(
    const float* __restrict__ A, const float* __restrict__ W, int M,
    int m0, int n0, int k0, bool relu,
    float (*As)[128], float (*Bs)[128], int tid)
{
    const int arow = tid >> 2;
    const int acol = (tid & 3) * 4;
    const int brow = tid >> 5;
    const int bcol = (tid & 31) * 4;
#pragma unroll
    for (int i = 0; i < 2; i++) {
        int r = m0 + arow + i * 64;
        int rc = r < M ? r : M - 1;
        float4 v = *(const float4*)(A + (size_t)rc * FF + k0 + acol);
        if (relu) {
            v.x = fmaxf(v.x, 0.f); v.y = fmaxf(v.y, 0.f);
            v.z = fmaxf(v.z, 0.f); v.w = fmaxf(v.w, 0.f);
        }
        As[acol + 0][arow + i * 64] = v.x;
        As[acol + 1][arow + i * 64] = v.y;
        As[acol + 2][arow + i * 64] = v.z;
        As[acol + 3][arow + i * 64] = v.w;
    }
#pragma unroll
    for (int i = 0; i < 2; i++) {
        int kr = brow + i * 8;
        float4 v = *(const float4*)(W + (size_t)(k0 + kr) * FF + n0 + bcol);
        *(float4*)&Bs[kr][bcol] = v;
    }
}

template<bool RELU, bool SCORES>
__global__ void __launch_bounds__(256) k_gemm256(const float* __restrict__ A,
                                                 const float* __restrict__ W,
                                                 float* __restrict__ C, int M,
                                                 const float* __restrict__ a_s,
                                                 const float* __restrict__ a_d,
                                                 float* __restrict__ hs,
                                                 float* __restrict__ hd) {
    __shared__ float As[2][16][128];
    __shared__ float Bs[2][16][128];
    const int tid = threadIdx.x;
    const int m0 = blockIdx.x * 128;
    const int n0 = blockIdx.y * 128;
    const int tx = tid & 15, ty = tid >> 4;

    u64t acc[8][4];
#pragma unroll
    for (int i = 0; i < 8; i++)
#pragma unroll
        for (int j = 0; j < 4; j++) acc[i][j] = 0ull;

    gemm_load_tile(A, W, M, m0, n0, 0, RELU, As[0], Bs[0], tid);
    __syncthreads();

    int buf = 0;
    for (int k0 = 0; k0 < 256; k0 += 16) {
        if (k0 < 240)
            gemm_load_tile(A, W, M, m0, n0, k0 + 16, RELU, As[buf ^ 1], Bs[buf ^ 1], tid);
#pragma unroll
        for (int kk = 0; kk < 16; kk++) {
            float4 av0 = *(const float4*)&As[buf][kk][ty * 8];
            float4 av1 = *(const float4*)&As[buf][kk][ty * 8 + 4];
            float4 bv0 = *(const float4*)&Bs[buf][kk][tx * 8];
            float4 bv1 = *(const float4*)&Bs[buf][kk][tx * 8 + 4];
            u64t bp[4];
            bp[0] = packf2(bv0.x, bv0.y);
            bp[1] = packf2(bv0.z, bv0.w);
            bp[2] = packf2(bv1.x, bv1.y);
            bp[3] = packf2(bv1.z, bv1.w);
            u64t ap[8];
            ap[0] = packf2(av0.x, av0.x);
            ap[1] = packf2(av0.y, av0.y);
            ap[2] = packf2(av0.z, av0.z);
            ap[3] = packf2(av0.w, av0.w);
            ap[4] = packf2(av1.x, av1.x);
            ap[5] = packf2(av1.y, av1.y);
            ap[6] = packf2(av1.z, av1.z);
            ap[7] = packf2(av1.w, av1.w);
#pragma unroll
            for (int i = 0; i < 8; i++)
#pragma unroll
                for (int j = 0; j < 4; j++) fma2(acc[i][j], ap[i], bp[j], acc[i][j]);
        }
        __syncthreads();
        buf ^= 1;
    }

    float as0[8], ad0[8];
    if (SCORES) {
#pragma unroll
        for (int j = 0; j < 8; j++) {
            as0[j] = __ldg(a_s + n0 + tx * 8 + j);
            ad0[j] = __ldg(a_d + n0 + tx * 8 + j);
        }
    }

#pragma unroll
    for (int i = 0; i < 8; i++) {
        int r = m0 + ty * 8 + i;
        float v[8];
        unpackf2(v[0], v[1], acc[i][0]);
        unpackf2(v[2], v[3], acc[i][1]);
        unpackf2(v[4], v[5], acc[i][2]);
        unpackf2(v[6], v[7], acc[i][3]);
        if (r < M) {
            *(float4*)(C + (size_t)r * FF + n0 + tx * 8)     = make_float4(v[0], v[1], v[2], v[3]);
            *(float4*)(C + (size_t)r * FF + n0 + tx * 8 + 4) = make_float4(v[4], v[5], v[6], v[7]);
        }
        if (SCORES) {
            float ps = 0.f, pd = 0.f;
#pragma unroll
            for (int j = 0; j < 8; j++) { ps += v[j] * as0[j]; pd += v[j] * ad0[j]; }
#pragma unroll
            for (int o = 8; o > 0; o >>= 1) {
                ps += __shfl_xor_sync(0xffffffffu, ps, o);
                pd += __shfl_xor_sync(0xffffffffu, pd, o);
            }
            if ((tid & 15) == 0 && r < M) {
                atomicAdd(hs + r, ps);
                atomicAdd(hd + r, pd);
            }
        }
    }
}

// ---------------- GCN gather: warp per node (combined graph) ----------------
__global__ void k_gcn_gather(const int* __restrict__ off, const int* __restrict__ csr,
                             const float* __restrict__ h, float* __restrict__ out,
                             const float* __restrict__ dinv,
                             const float* __restrict__ bab, const float* __restrict__ bag,
                             int n, int nsplit) {
    int w = (blockIdx.x * blockDim.x + threadIdx.x) >> 5;
    int lane = threadIdx.x & 31;
    if (w >= n) return;
    int e0 = off[w], e1 = off[w + 1];
    float dv = dinv[w];
    float4 a0 = make_float4(0.f, 0.f, 0.f, 0.f);
    float4 a1 = make_float4(0.f, 0.f, 0.f, 0.f);
    for (int base = e0; base < e1; base += 32) {
        int e = base + lane;
        int idx = (e < e1) ? csr[e] : 0;
        float wv = (e < e1) ? dinv[idx] : 0.f;
        int cnt = min(32, e1 - base);
        for (int k = 0; k < cnt; k++) {
            int s = __shfl_sync(0xffffffffu, idx, k);
            float ws = __shfl_sync(0xffffffffu, wv, k);
            const float4* hp = (const float4*)(h + (size_t)s * FF) + lane;
            float4 v0 = hp[0];
            float4 v1 = hp[32];
            a0.x += v0.x * ws; a0.y += v0.y * ws; a0.z += v0.z * ws; a0.w += v0.w * ws;
            a1.x += v1.x * ws; a1.y += v1.y * ws; a1.z += v1.z * ws; a1.w += v1.w * ws;
        }
    }
    {
        const float4* hp = (const float4*)(h + (size_t)w * FF) + lane;
        float4 v0 = hp[0], v1 = hp[32];
        a0.x += v0.x * dv; a0.y += v0.y * dv; a0.z += v0.z * dv; a0.w += v0.w * dv;
        a1.x += v1.x * dv; a1.y += v1.y * dv; a1.z += v1.z * dv; a1.w += v1.w * dv;
    }
    const float* b = (w < nsplit) ? bab : bag;
    float4 b0 = *((const float4*)b + lane);
    float4 b1 = *((const float4*)b + lane + 32);
    float4 o0 = make_float4(a0.x * dv + b0.x, a0.y * dv + b0.y, a0.z * dv + b0.z, a0.w * dv + b0.w);
    float4 o1 = make_float4(a1.x * dv + b1.x, a1.y * dv + b1.y, a1.z * dv + b1.z, a1.w * dv + b1.w);
    float4* op = (float4*)(out + (size_t)w * FF) + lane;
    op[0] = o0;
    op[32] = o1;
}

// ---------------- BN (multi-segment stats) ----------------
__global__ void k_stats4(const float* __restrict__ p0, const float* __restrict__ p1,
                         const float* __restrict__ p2, const float* __restrict__ p3,
                         int nrows, float* __restrict__ sum, float* __restrict__ sq) {
    int seg = blockIdx.y;
    const float* X = (seg == 0) ? p0 : (seg == 1) ? p1 : (seg == 2) ? p2 : p3;
    int c = threadIdx.x;
    float s = 0.f, q = 0.f;
    for (int r = blockIdx.x; r < nrows; r += gridDim.x) {
        float v = X[(size_t)r * FF + c];
        s += v; q += v * v;
    }
    atomicAdd(&sum[seg * 256 + c], s);
    atomicAdd(&sq[seg * 256 + c], q);
}

__global__ void k_finalize(const float* __restrict__ sum, const float* __restrict__ sq,
                           float* __restrict__ mu, float* __restrict__ rstd, int n, int cnt) {
    int i = blockIdx.x * blockDim.x + threadIdx.x;
    if (i >= cnt) return;
    float m = sum[i] / n;
    mu[i] = m;
    rstd[i] = rsqrtf(sq[i] / n - m * m + EPS);
}

// merged bn+relu over both halves (param set selected by node index)
__global__ void k_bnrelu2(const float* __restrict__ X, float* __restrict__ Y,
                          const float* __restrict__ mu, const float* __restrict__ rstd,
                          const float* __restrict__ ga, const float* __restrict__ ba,
                          const float* __restrict__ gb, const float* __restrict__ bb,
                          int n, int nsplit) {
    size_t idx = (size_t)blockIdx.x * blockDim.x + threadIdx.x;
    if (idx >= (size_t)n * FF) return;
    int node = (int)(idx >> 8), c = (int)(idx & 255);
    bool lo = node < nsplit;
    int mc = lo ? c : c + 256;
    const float* g = lo ? ga : gb;
    const float* b = lo ? ba : bb;
    float v = (X[idx] - mu[mc]) * rstd[mc] * g[c] + b[c];
    Y[idx] = fmaxf(v, 0.f);
}

// ---------------- fused GAT per node ----------------
__global__ void k_gat_node(const int* __restrict__ off, const int* __restrict__ csr,
                           const float* __restrict__ h, float* __restrict__ out,
                           const float* __restrict__ hs, const float* __restrict__ hd,
                           const float* __restrict__ b, int n) {
    int w = (blockIdx.x * blockDim.x + threadIdx.x) >> 5;
    int lane = threadIdx.x & 31;
    if (w >= n) return;
    int e0 = off[w], e1 = off[w + 1];
    float hdn = hd[w];
    float self_e = lrelu(hs[w] + hdn);

    float m = (lane == 0) ? self_e : NINF;
    float s = (lane == 0) ? 1.f : 0.f;
    for (int e = e0 + lane; e < e1; e += 32) {
        float v = lrelu(hs[csr[e]] + hdn);
        if (v > m) { s = s * __expf(m - v) + 1.f; m = v; }
        else       { s += __expf(v - m); }
    }
#pragma unroll
    for (int o = 16; o > 0; o >>= 1) {
        float mo = __shfl_xor_sync(0xffffffffu, m, o);
        float so = __shfl_xor_sync(0xffffffffu, s, o);
        float mn = fmaxf(m, mo);
        s = s * __expf(m - mn) + so * __expf(mo - mn);
        m = mn;
    }
    float inv = 1.f / s;

    float4 a0, a1;
    {
        float sa = __expf(self_e - m) * inv;
        const float4* hp = (const float4*)(h + (size_t)w * FF) + lane;
        float4 v0 = hp[0], v1 = hp[32];
        a0 = make_float4(v0.x * sa, v0.y * sa, v0.z * sa, v0.w * sa);
        a1 = make_float4(v1.x * sa, v1.y * sa, v1.z * sa, v1.w * sa);
    }
    for (int base = e0; base < e1; base += 32) {
        int e = base + lane;
        int idx = (e < e1) ? csr[e] : 0;
        float al = 0.f;
        if (e < e1) al = __expf(lrelu(hs[idx] + hdn) - m) * inv;
        int cnt = min(32, e1 - base);
        for (int k = 0; k < cnt; k++) {
            int sn = __shfl_sync(0xffffffffu, idx, k);
            float av = __shfl_sync(0xffffffffu, al, k);
            const float4* hp = (const float4*)(h + (size_t)sn * FF) + lane;
            float4 v0 = hp[0];
            float4 v1 = hp[32];
            a0.x += v0.x * av; a0.y += v0.y * av; a0.z += v0.z * av; a0.w += v0.w * av;
            a1.x += v1.x * av; a1.y += v1.y * av; a1.z += v1.z * av; a1.w += v1.w * av;
        }
    }
    float4 b0 = *((const float4*)b + lane);
    float4 b1 = *((const float4*)b + lane + 32);
    a0.x += b0.x; a0.y += b0.y; a0.z += b0.z; a0.w += b0.w;
    a1.x += b1.x; a1.y += b1.y; a1.z += b1.z; a1.w += b1.w;
    float4* op = (float4*)(out + (size_t)w * FF) + lane;
    op[0] = a0;
    op[32] = a1;
}

// ---------------- final: relu(bn(concat[X,H])) @ Wfc + bfc ----------------
__global__ void k_final(const float* __restrict__ Xp, const float* __restrict__ Hp,
                        const float* __restrict__ mu, const float* __restrict__ rstd,
                        const float* __restrict__ g, const float* __restrict__ b,
                        const float* __restrict__ Wfc, const float* __restrict__ bfc,
                        float* __restrict__ out, int n) {
    int w = (blockIdx.x * blockDim.x + threadIdx.x) >> 5;
    int lane = threadIdx.x & 31;
    if (w >= n) return;
    float acc = 0.f;
#pragma unroll
    for (int j = 0; j < 16; j++) {
        int c = j * 32 + lane;
        float v = (c < FF) ? Xp[(size_t)w * FF + c] : Hp[(size_t)w * FF + (c - FF)];
        v = (v - mu[c]) * rstd[c] * g[c] + b[c];
        v = fmaxf(v, 0.f);
        acc += v * __ldg(Wfc + c);
    }
#pragma unroll
    for (int off = 16; off > 0; off >>= 1) acc += __shfl_down_sync(0xffffffffu, acc, off);
    if (lane == 0) out[w] = acc + bfc[0];
}

// ---------------- host orchestration ----------------
static void gat_layer(const float* xin, bool relu_in, const float* W, const float* a_s,
                      const float* a_d, const float* b, float* hbuf, float* outbuf,
                      const int* off, const int* csr, float* sc) {
    k_fill<<<(2 * NTOT + 255) / 256, 256>>>(sc, 0.f, 2 * NTOT);
    dim3 gg((NTOT + 127) / 128, 2);
    if (relu_in) k_gemm256<true,  true><<<gg, 256>>>(xin, W, hbuf, NTOT, a_s, a_d, sc, sc + NTOT);
    else         k_gemm256<false, true><<<gg, 256>>>(xin, W, hbuf, NTOT, a_s, a_d, sc, sc + NTOT);
    k_gat_node<<<(NTOT * 32 + 255) / 256, 256>>>(off, csr, hbuf, outbuf, sc, sc + NTOT, b, NTOT);
}

extern "C" void kernel_launch(void* const* d_in, const int* in_sizes, int n_in,
                              void* d_out, int out_size) {
    const float* x_ab   = (const float*)d_in[0];
    const float* x_ag   = (const float*)d_in[1];
    const float* W_gcn  = (const float*)d_in[2];
    const float* b_gcn  = (const float*)d_in[3];
    const float* g1     = (const float*)d_in[4];
    const float* be1    = (const float*)d_in[5];
    const float* W_aggcn= (const float*)d_in[6];
    const float* b_aggcn= (const float*)d_in[7];
    const float* ag_g1  = (const float*)d_in[8];
    const float* ag_be1 = (const float*)d_in[9];
    const float* W_gat  = (const float*)d_in[10];
    const float* a_src  = (const float*)d_in[11];
    const float* a_dst  = (const float*)d_in[12];
    const float* b_gat  = (const float*)d_in[13];
    const float* W_gat2 = (const float*)d_in[14];
    const float* a_src2 = (const float*)d_in[15];
    const float* a_dst2 = (const float*)d_in[16];
    const float* b_gat2 = (const float*)d_in[17];
    const float* ag_g2  = (const float*)d_in[18];
    const float* ag_be2 = (const float*)d_in[19];
    const float* W_agfc = (const float*)d_in[20];
    const float* b_agfc = (const float*)d_in[21];
    const float* g2     = (const float*)d_in[22];
    const float* be2    = (const float*)d_in[23];
    const float* W_fc   = (const float*)d_in[24];
    const float* b_fc   = (const float*)d_in[25];
    const int* e_ab     = (const int*)d_in[26];
    const int* e_ag     = (const int*)d_in[27];
    const int* e_d      = (const int*)d_in[28];
    float* out = (float*)d_out;

    float *pX, *pA, *pB, *pdinv, *psc, *pss, *pmu, *prstd;
    int *pdegi, *pcur, *poff_g, *poff_d, *pcsr_g, *pcsr_d, *ppart;
    cudaGetSymbolAddress((void**)&pX, g_X);
    cudaGetSymbolAddress((void**)&pA, g_A);
    cudaGetSymbolAddress((void**)&pB, g_B);
    cudaGetSymbolAddress((void**)&pdinv, g_dinv);
    cudaGetSymbolAddress((void**)&psc, g_sc);
    cudaGetSymbolAddress((void**)&pss, g_sumsq);
    cudaGetSymbolAddress((void**)&pmu, g_mu);
    cudaGetSymbolAddress((void**)&prstd, g_rstd);
    cudaGetSymbolAddress((void**)&pdegi, g_degi);
    cudaGetSymbolAddress((void**)&pcur, g_cur);
    cudaGetSymbolAddress((void**)&poff_g, g_off_g);
    cudaGetSymbolAddress((void**)&poff_d, g_off_d);
    cudaGetSymbolAddress((void**)&pcsr_g, g_csr_g);
    cudaGetSymbolAddress((void**)&pcsr_d, g_csr_d);
    cudaGetSymbolAddress((void**)&ppart, g_partials);
    float* psum = pss;
    float* psq  = pss + 1024;

    const int* eab_src = e_ab;           const int* eab_dst = e_ab + EAB;
    const int* eag_src = e_ag;           const int* eag_dst = e_ag + EAG;
    const int* ed_src  = e_d;            const int* ed_dst  = e_d + ED;

    const int NB_TOT = (NTOT + SCAN_CHUNK - 1) / SCAN_CHUNK;   // 40

    // ---- launches 0-2: degree ----
    k_filli<<<(NTOT + 255) / 256, 256>>>(pdegi, 0, NTOT);                       // 0
    k_deg<<<(EAB + 255) / 256, 256>>>(eab_dst, EAB, pdegi);                     // 1
    k_deg<<<(EAG + 255) / 256, 256>>>(eag_dst, EAG, pdegi + NAB);               // 2
    // ---- launch 3: first GEMM (profiled by ncu -s 5 given 2 harness launches) ----
    {
        dim3 gab((NAB + 127) / 128, 2);
        k_gemm256<false, false><<<gab, 256>>>(x_ab, W_gcn, pB, NAB,
                                              nullptr, nullptr, nullptr, nullptr);   // 3
        k_gemm256<false, false><<<gab, 256>>>(x_ag, W_aggcn, pB + (size_t)NAB * FF, NAB,
                                              nullptr, nullptr, nullptr, nullptr);   // 4
    }
    k_dinv<<<(NTOT + 255) / 256, 256>>>(pdegi, pdinv, NTOT);

    // ---- combined GCN CSR over NTOT ----
    k_scan1<<<NB_TOT, SCAN_T>>>(pdegi, NTOT, ppart);
    k_scan2<<<1, 64>>>(ppart, NB_TOT, poff_g, NTOT);
    k_scan3<<<NB_TOT, SCAN_T>>>(pdegi, NTOT, ppart, poff_g);
    k_copyi<<<(NTOT + 255) / 256, 256>>>(poff_g, pcur, NTOT);
    k_scatter<<<(EAB + 255) / 256, 256>>>(eab_src, eab_dst, EAB, pcur, pcsr_g, 0, 0);
    k_scatter<<<(EAG + 255) / 256, 256>>>(eag_src, eag_dst, EAG, pcur, pcsr_g, NAB, NAB);

    // ---- GCN aggregate (gather) into g_A ----
    k_gcn_gather<<<(NTOT * 32 + 255) / 256, 256>>>(poff_g, pcsr_g, pB, pA, pdinv,
                                                   b_gcn, b_aggcn, NTOT, NAB);

    // ---- CSR build: d graph ----
    k_filli<<<(NTOT + 255) / 256, 256>>>(pdegi, 0, NTOT);
    k_deg<<<(ED + 255) / 256, 256>>>(ed_dst, ED, pdegi);
    k_scan1<<<NB_TOT, SCAN_T>>>(pdegi, NTOT, ppart);
    k_scan2<<<1, 64>>>(ppart, NB_TOT, poff_d, NTOT);
    k_scan3<<<NB_TOT, SCAN_T>>>(pdegi, NTOT, ppart, poff_d);
    k_copyi<<<(NTOT + 255) / 256, 256>>>(poff_d, pcur, NTOT);
    k_scatter<<<(ED + 255) / 256, 256>>>(ed_src, ed_dst, ED, pcur, pcsr_d, 0, 0);

    // ---- BN1 + relu -> g_X ----
    k_fill<<<8, 256>>>(pss, 0.f, 2048);
    {
        dim3 gs(96, 2);
        k_stats4<<<gs, 256>>>(pA, pA + (size_t)NAB * FF, nullptr, nullptr, NAB, psum, psq);
    }
    k_finalize<<<2, 256>>>(psum, psq, pmu, prstd, NAB, 512);
    k_bnrelu2<<<((size_t)NTOT * FF + 255) / 256, 256>>>(pA, pX, pmu, prstd,
                                                        g1, be1, ag_g1, ag_be1, NTOT, NAB);

    // ---- GAT1: g_X -> g_A ; GAT2: relu(g_A) -> g_A ----
    gat_layer(pX, false, W_gat,  a_src,  a_dst,  b_gat,  pB, pA, poff_d, pcsr_d, psc);
    gat_layer(pA, true,  W_gat2, a_src2, a_dst2, b_gat2, pB, pA, poff_d, pcsr_d, psc);

    // ---- final BN stats over concat halves ----
    k_fill<<<8, 256>>>(pss, 0.f, 2048);
    {
        dim3 gs(96, 4);
        k_stats4<<<gs, 256>>>(pA, pX, pA + (size_t)NAB * FF, pX + (size_t)NAB * FF,
                              NAB, psum, psq);
    }
    k_finalize<<<4, 256>>>(psum, psq, pmu, prstd, NAB, 1024);

    // ---- final outputs ----
    k_final<<<(NAB * 32 + 255) / 256, 256>>>(pA, pX, pmu, prstd, g2, be2, W_fc, b_fc,
                                             out, NAB);
    k_final<<<(NAG * 32 + 255) / 256, 256>>>(pA + (size_t)NAB * FF, pX + (size_t)NAB * FF,
                                             pmu + 512, prstd + 512, ag_g2, ag_be2,
                                             W_agfc, b_agfc, out + NAB, NAG);
}